// round 13
// baseline (speedup 1.0000x reference)
#include <cuda_runtime.h>
#include <cuda_bf16.h>
#include <math.h>

#define CDIV(a,b) (((a)+(b)-1)/(b))

// Dimensions: B=512, SC=48, ST=16, E=512, H=256, N_CHARS=128, N_TAGS=64
constexpr size_t SZ(size_t n) { return (n + 255) & ~(size_t)255; }

constexpr size_t O_CS    = 0;                                    // [512,48,192]
constexpr size_t O_TS    = O_CS    + SZ(24576ull*192);           // [512,16,128]
constexpr size_t O_DECIN = O_TS    + SZ(8192ull*128);            // [512,48,128]
constexpr size_t O_XCF   = O_DECIN + SZ(24576ull*128);           // [512,48,1024]
constexpr size_t O_XCB   = O_XCF   + SZ(24576ull*1024);
constexpr size_t O_XTF   = O_XCB   + SZ(24576ull*1024);          // [512,16,1024]
constexpr size_t O_XTB   = O_XTF   + SZ(8192ull*1024);
constexpr size_t O_XDEC  = O_XTB   + SZ(8192ull*1024);           // [512,48,2048]
constexpr size_t O_CO    = O_XDEC  + SZ(24576ull*2048);          // [512,48,512]
constexpr size_t O_TO    = O_CO    + SZ(24576ull*512);           // [512,16,512]
constexpr size_t O_HS    = O_TO    + SZ(8192ull*512);            // [512,48,512]
constexpr size_t O_CCF   = O_HS    + SZ(24576ull*512);           // 2x[512,256]
constexpr size_t O_CCB   = O_CCF   + SZ(2ull*512*256);
constexpr size_t O_CTF   = O_CCB   + SZ(2ull*512*256);
constexpr size_t O_CTB   = O_CTF   + SZ(2ull*512*256);
constexpr size_t O_DC    = O_CTB   + SZ(2ull*512*256);           // 2x[512,512]
constexpr size_t O_H0    = O_DC    + SZ(2ull*512*512);
constexpr size_t O_C0    = O_H0    + SZ(512ull*512);
constexpr size_t O_QC    = O_C0    + SZ(512ull*512);             // [512,48,512]
constexpr size_t O_QT    = O_QC    + SZ(24576ull*512);
constexpr size_t O_KVC   = O_QT    + SZ(24576ull*512);           // [512,48,1024]
constexpr size_t O_KVT   = O_KVC   + SZ(24576ull*1024);          // [512,16,1024]
constexpr size_t O_OC    = O_KVT   + SZ(8192ull*1024);           // [512,48,512]
constexpr size_t O_OT    = O_OC    + SZ(24576ull*512);
constexpr size_t O_CAT   = O_OT    + SZ(24576ull*512);           // [24576,1024]
constexpr size_t O_LOG   = O_CAT   + SZ(24576ull*1024);          // [24576,128]
// pre-split LSTM weights (uint words): hi then lo, contiguous per matrix
constexpr size_t O_WCF   = O_LOG   + SZ(24576ull*128);           // enc char fwd
constexpr size_t O_WCB   = O_WCF   + SZ(2ull*131072);
constexpr size_t O_WTF   = O_WCB   + SZ(2ull*131072);
constexpr size_t O_WTB   = O_WTF   + SZ(2ull*131072);
constexpr size_t O_WD    = O_WTB   + SZ(2ull*131072);            // decoder
constexpr size_t O_END   = O_WD    + SZ(2ull*524288);

__device__ float g_scratch[O_END];

// ---------------------------------------------------------------------------
// grid-wide barrier for persistent kernels (always 128 blocks)
// ---------------------------------------------------------------------------
__device__ unsigned g_cnt = 0;
__device__ unsigned g_gen = 0;

__device__ __forceinline__ void grid_barrier128() {
    __syncthreads();
    __threadfence();
    if (threadIdx.x == 0) {
        volatile unsigned* vg = &g_gen;
        unsigned my = *vg;
        if (atomicInc(&g_cnt, 127u) == 127u) {
            atomicAdd(&g_gen, 1u);
        } else {
            while (*vg == my) __nanosleep(64);
        }
    }
    __syncthreads();
}

// ---------------------------------------------------------------------------
__global__ void prep_kernel(const int* __restrict__ li,
                            const float* __restrict__ char_seq,
                            const float* __restrict__ tagset,
                            const float* __restrict__ lang_embeds,
                            float* __restrict__ cs, float* __restrict__ ts) {
    int idx = blockIdx.x * blockDim.x + threadIdx.x;
    const int n1 = 512 * 48 * 192;
    const int n2 = 512 * 16 * 128;
    if (idx < n1) {
        int b = idx / (48 * 192);
        int rem = idx - b * 48 * 192;
        int s = rem / 192, k = rem - s * 192;
        float v;
        if (k < 128) v = char_seq[(b * 48 + s) * 128 + k];
        else         v = lang_embeds[li[li[b]] * 64 + (k - 128)];
        cs[idx] = v;
    } else if (idx < n1 + n2) {
        int j = idx - n1;
        int b = j / (16 * 128);
        int rem = j - b * 16 * 128;
        int s = rem / 128, k = rem - s * 128;
        float v;
        if (k < 64) v = tagset[(b * 16 + s) * 64 + k];
        else        v = lang_embeds[li[li[b]] * 64 + (k - 64)];
        ts[j] = v;
    }
}

__global__ void build_decin(const float* __restrict__ labels, float* __restrict__ decin) {
    int idx = blockIdx.x * blockDim.x + threadIdx.x;
    if (idx >= 512 * 48 * 128) return;
    int t = (idx >> 7) % 48;
    decin[idx] = (t == 0) ? 0.f : labels[idx];
}

// ---------------------------------------------------------------------------
// bf16x3 helpers. x = hi + lo (both bf16): per-product error ~2^-18.
// D += Ah*Bh + Ah*Bl + Al*Bh with fp32 accumulate (m16n8k16).
// ---------------------------------------------------------------------------
__device__ __forceinline__ void split_bf(float x0, float x1,
                                         unsigned& hi2, unsigned& lo2) {
    unsigned h;
    asm("cvt.rn.bf16x2.f32 %0, %1, %2;" : "=r"(h) : "f"(x1), "f"(x0));
    float h0 = __uint_as_float(h << 16);
    float h1 = __uint_as_float(h & 0xffff0000u);
    float l0 = x0 - h0;
    float l1 = x1 - h1;
    unsigned l;
    asm("cvt.rn.bf16x2.f32 %0, %1, %2;" : "=r"(l) : "f"(l1), "f"(l0));
    hi2 = h; lo2 = l;
}

__device__ __forceinline__ void mma16bf(float* c, const unsigned* a, const unsigned* b) {
    asm volatile(
        "mma.sync.aligned.m16n8k16.row.col.f32.bf16.bf16.f32 "
        "{%0,%1,%2,%3}, {%4,%5,%6,%7}, {%8,%9}, {%0,%1,%2,%3};\n"
        : "+f"(c[0]), "+f"(c[1]), "+f"(c[2]), "+f"(c[3])
        : "r"(a[0]), "r"(a[1]), "r"(a[2]), "r"(a[3]), "r"(b[0]), "r"(b[1]));
}

// k2 permutation within each 8-word group so the fragment pair (k2, k2+4)
// is one LDS.64: pos = group*8 + (k2&3)*2 + ((k2>>2)&1)
__device__ __forceinline__ int permk2(int k2) {
    return (k2 >> 3) * 8 + (k2 & 3) * 2 + ((k2 >> 2) & 1);
}

// pre-split a weight matrix into packed bf16x2 hi/lo arrays, [rows][H/2] rm
__global__ void wsplit_kernel(const float* __restrict__ w,
                              unsigned* __restrict__ hi,
                              unsigned* __restrict__ lo, int n2) {
    int idx = blockIdx.x * blockDim.x + threadIdx.x;
    if (idx >= n2) return;
    float x0 = w[idx * 2], x1 = w[idx * 2 + 1];
    unsigned h, l;
    split_bf(x0, x1, h, l);
    hi[idx] = h;
    lo[idx] = l;
}

// ---------------------------------------------------------------------------
// GEMM: C[m,n] = sum_k A[m,k]*W[n,k] + bias[n]. 128x128 tile, k-step 32,
// double-buffered, 512 threads = 16 warps (4m x 4n), warp tile 32x32.
// smem (uint32 words): Ah[128*24] Al Bh Bl; rows stride 24 words.
// Stage = 12288 words; double buffer = 98304 bytes.
// ---------------------------------------------------------------------------
__device__ __forceinline__ void g_ldg(const float* __restrict__ A,
                                      const float* __restrict__ W,
                                      int K, int bm, int bn, int k0, int tid,
                                      float4* av, float4* wv) {
#pragma unroll
    for (int i = 0; i < 2; i++) {
        int idx = tid + i * 512;
        int row = idx >> 3, fc = idx & 7;
        av[i] = *(const float4*)(A + (size_t)(bm + row) * K + k0 + fc * 4);
        wv[i] = *(const float4*)(W + (size_t)(bn + row) * K + k0 + fc * 4);
    }
}

__device__ __forceinline__ void g_sts(unsigned* __restrict__ buf, int tid,
                                      const float4* av, const float4* wv) {
    unsigned* Ah = buf;
    unsigned* Al = buf + 3072;
    unsigned* Bh = buf + 6144;
    unsigned* Bl = buf + 9216;
#pragma unroll
    for (int i = 0; i < 2; i++) {
        int idx = tid + i * 512;
        int row = idx >> 3, fc = idx & 7;
        int pa = row * 24 + permk2(fc * 2);
        int pb = row * 24 + permk2(fc * 2 + 1);
        unsigned h, l;
        split_bf(av[i].x, av[i].y, h, l); Ah[pa] = h; Al[pa] = l;
        split_bf(av[i].z, av[i].w, h, l); Ah[pb] = h; Al[pb] = l;
        split_bf(wv[i].x, wv[i].y, h, l); Bh[pa] = h; Bl[pa] = l;
        split_bf(wv[i].z, wv[i].w, h, l); Bh[pb] = h; Bl[pb] = l;
    }
}

__device__ __forceinline__ void g_compute(const unsigned* __restrict__ buf,
                                          int wm, int wn, int gid, int tig,
                                          float (&acc)[2][4][4]) {
    const unsigned* Ah = buf;
    const unsigned* Al = buf + 3072;
    const unsigned* Bh = buf + 6144;
    const unsigned* Bl = buf + 9216;
#pragma unroll
    for (int s = 0; s < 2; s++) {
        unsigned ah[2][4], al[2][4];
#pragma unroll
        for (int mt = 0; mt < 2; mt++) {
            int o = (wm * 32 + mt * 16 + gid) * 24 + s * 8 + tig * 2;
            uint2 p = *(const uint2*)(Ah + o);
            uint2 q = *(const uint2*)(Ah + o + 192);   // +8 rows
            ah[mt][0] = p.x; ah[mt][2] = p.y; ah[mt][1] = q.x; ah[mt][3] = q.y;
            uint2 r = *(const uint2*)(Al + o);
            uint2 t = *(const uint2*)(Al + o + 192);
            al[mt][0] = r.x; al[mt][2] = r.y; al[mt][1] = t.x; al[mt][3] = t.y;
        }
        unsigned bh[4][2], bl[4][2];
#pragma unroll
        for (int j = 0; j < 4; j++) {
            int o = (wn * 32 + j * 8 + gid) * 24 + s * 8 + tig * 2;
            uint2 p = *(const uint2*)(Bh + o);
            bh[j][0] = p.x; bh[j][1] = p.y;
            uint2 q = *(const uint2*)(Bl + o);
            bl[j][0] = q.x; bl[j][1] = q.y;
        }
#pragma unroll
        for (int mt = 0; mt < 2; mt++)
#pragma unroll
            for (int j = 0; j < 4; j++) {
                float* c = acc[mt][j];
                mma16bf(c, ah[mt], bh[j]);
                mma16bf(c, ah[mt], bl[j]);
                mma16bf(c, al[mt], bh[j]);
            }
    }
}

__global__ __launch_bounds__(512) void gemm_mma(
    const float* __restrict__ A, const float* __restrict__ W,
    const float* __restrict__ bias, float* __restrict__ C,
    int M, int N, int K, int ldc)
{
    extern __shared__ unsigned gsb[];
    unsigned* buf0 = gsb;
    unsigned* buf1 = gsb + 12288;
    const int bm = blockIdx.y * 128;
    const int bn = blockIdx.x * 128;
    const int tid = threadIdx.x;
    const int wid = tid >> 5, lane = tid & 31;
    const int wm = wid >> 2, wn = wid & 3;
    const int gid = lane >> 2, tig = lane & 3;

    float acc[2][4][4];
#pragma unroll
    for (int i = 0; i < 2; i++)
#pragma unroll
        for (int j = 0; j < 4; j++)
#pragma unroll
            for (int r = 0; r < 4; r++) acc[i][j][r] = 0.f;

    const int NT = K >> 5;
    float4 av[2], wv[2];

    g_ldg(A, W, K, bm, bn, 0, tid, av, wv);
    g_sts(buf0, tid, av, wv);
    __syncthreads();
    g_ldg(A, W, K, bm, bn, 32, tid, av, wv);

    for (int kt = 0; kt < NT; kt += 2) {
        g_sts(buf1, tid, av, wv);
        if (kt + 2 < NT) g_ldg(A, W, K, bm, bn, (kt + 2) * 32, tid, av, wv);
        g_compute(buf0, wm, wn, gid, tig, acc);
        __syncthreads();
        if (kt + 2 < NT) {
            g_sts(buf0, tid, av, wv);
            if (kt + 3 < NT) g_ldg(A, W, K, bm, bn, (kt + 3) * 32, tid, av, wv);
        }
        g_compute(buf1, wm, wn, gid, tig, acc);
        __syncthreads();
    }

#pragma unroll
    for (int mt = 0; mt < 2; mt++)
#pragma unroll
        for (int nt = 0; nt < 4; nt++) {
            int row = bm + wm * 32 + mt * 16 + gid;
            int col = bn + wn * 32 + nt * 8 + tig * 2;
            float b0 = bias[col], b1 = bias[col + 1];
            float* c = acc[mt][nt];
            float* p0 = C + (size_t)row * ldc + col;
            float* p1 = C + (size_t)(row + 8) * ldc + col;
            p0[0] = c[0] + b0; p0[1] = c[1] + b1;
            p1[0] = c[2] + b0; p1[1] = c[3] + b1;
        }
}

// ---------------------------------------------------------------------------
// Persistent tensor-core LSTM (bf16x3, PRE-SPLIT weights).
// 128 blocks x 512 threads, 1 block/SM, software grid barrier between steps.
// Block tile: BM batch x 64 j x 4 gates (N=256), 16 warps, each warp N=16.
// Weights come from pre-split hi/lo arrays ([4H, H/2] packed bf16x2): the
// steady-state weight path is LDG(uint2) -> STS (no cvt).
// smem stage (words): Ah[BM*24] Al[BM*24] Bh[256*24] Bl[256*24] = 13824;
// double buffer = 110592 bytes. Epilogue reuses smem as float EB[BM][260].
// ---------------------------------------------------------------------------
struct PChain {
    const float*    xg0;  long dxg;   // Xg(t) = xg0 + t*dxg
    float*          ho0;  long dho;   // ho(t) = ho0 + t*dho; hp(t)=ho(t-1)
    const float*    hp_init;          // t==0 h (nullptr => zeros)
    const float*    cp_init;          // t==0 c (nullptr => zeros)
    const unsigned* whi;              // pre-split weights hi [4H][H/2]
    const unsigned* wlo;              // pre-split weights lo
    float*          cbuf;             // 2 x [512,H] ping-pong
    int ldx, ldh, ldo, ldh_init;
};
struct PArgs { PChain c[2]; };

__device__ __forceinline__ float sigm(float x) { return 1.f / (1.f + expf(-x)); }

template<int BM>
__device__ __forceinline__ void l_ldg(const float* hp, int ldh,
                                      const unsigned* whi, const unsigned* wlo,
                                      int H, int b0, int j0, int k0, int tid,
                                      float4* av, uint2* wh, uint2* wl) {
    if (tid < BM * 8) {
        int r = tid >> 3, fc = tid & 7;
        av[0] = *(const float4*)(hp + (size_t)(b0 + r) * ldh + k0 + fc * 4);
    }
    const int H2 = H >> 1;
#pragma unroll
    for (int i = 0; i < 4; i++) {
        int idx = tid + i * 512;
        int r = idx >> 3, fc = idx & 7;
        int g = r >> 6, jl = r & 63;
        size_t off = (size_t)(g * H + j0 + jl) * H2 + (k0 >> 1) + fc * 2;
        wh[i] = *(const uint2*)(whi + off);
        wl[i] = *(const uint2*)(wlo + off);
    }
}

template<int BM>
__device__ __forceinline__ void l_sts(unsigned* __restrict__ buf, int tid,
                                      const float4* av,
                                      const uint2* wh, const uint2* wl) {
    unsigned* Ah = buf;
    unsigned* Al = buf + BM * 24;
    unsigned* Bh = buf + 2 * BM * 24;
    unsigned* Bl = buf + 2 * BM * 24 + 6144;
    if (tid < BM * 8) {
        int r = tid >> 3, fc = tid & 7;
        int pa = r * 24 + permk2(fc * 2);
        int pb = r * 24 + permk2(fc * 2 + 1);
        unsigned h, l;
        split_bf(av[0].x, av[0].y, h, l); Ah[pa] = h; Al[pa] = l;
        split_bf(av[0].z, av[0].w, h, l); Ah[pb] = h; Al[pb] = l;
    }
#pragma unroll
    for (int i = 0; i < 4; i++) {
        int idx = tid + i * 512;
        int r = idx >> 3, fc = idx & 7;
        int pa = r * 24 + permk2(fc * 2);
        int pb = r * 24 + permk2(fc * 2 + 1);
        Bh[pa] = wh[i].x; Bh[pb] = wh[i].y;
        Bl[pa] = wl[i].x; Bl[pb] = wl[i].y;
    }
}

template<int BM>
__device__ __forceinline__ void l_compute(const unsigned* __restrict__ buf,
                                          int wn, int gid, int tig,
                                          float (&acc)[BM/16][2][4]) {
    constexpr int MT = BM / 16;
    const unsigned* Ah = buf;
    const unsigned* Al = buf + BM * 24;
    const unsigned* Bh = buf + 2 * BM * 24;
    const unsigned* Bl = buf + 2 * BM * 24 + 6144;
#pragma unroll
    for (int s = 0; s < 2; s++) {
        unsigned ah[MT][4], al[MT][4];
#pragma unroll
        for (int mt = 0; mt < MT; mt++) {
            int o = (mt * 16 + gid) * 24 + s * 8 + tig * 2;
            uint2 p = *(const uint2*)(Ah + o);
            uint2 q = *(const uint2*)(Ah + o + 192);
            ah[mt][0] = p.x; ah[mt][2] = p.y; ah[mt][1] = q.x; ah[mt][3] = q.y;
            uint2 r = *(const uint2*)(Al + o);
            uint2 t = *(const uint2*)(Al + o + 192);
            al[mt][0] = r.x; al[mt][2] = r.y; al[mt][1] = t.x; al[mt][3] = t.y;
        }
        unsigned bh[2][2], bl[2][2];
#pragma unroll
        for (int nj = 0; nj < 2; nj++) {
            int o = (wn * 16 + nj * 8 + gid) * 24 + s * 8 + tig * 2;
            uint2 p = *(const uint2*)(Bh + o);
            bh[nj][0] = p.x; bh[nj][1] = p.y;
            uint2 q = *(const uint2*)(Bl + o);
            bl[nj][0] = q.x; bl[nj][1] = q.y;
        }
#pragma unroll
        for (int mt = 0; mt < MT; mt++)
#pragma unroll
            for (int nj = 0; nj < 2; nj++) {
                float* c = acc[mt][nj];
                mma16bf(c, ah[mt], bh[nj]);
                mma16bf(c, ah[mt], bl[nj]);
                mma16bf(c, al[mt], bh[nj]);
            }
    }
}

template<int BM>
__device__ void lstm_body(const float* Xg, const float* hp, const float* cp,
                          const unsigned* whi, const unsigned* wlo,
                          float* ho, float* co,
                          int ldx, int ldh, int ldo, int H,
                          unsigned* sb, int j0, int b0, int tid) {
    constexpr int MT = BM / 16;
    constexpr int BUFSZ = (2 * BM + 512) * 24;   // 13824 for BM=32
    unsigned* buf0 = sb;
    unsigned* buf1 = sb + BUFSZ;
    const int lane = tid & 31;
    const int wn = tid >> 5;
    const int gid = lane >> 2, tig = lane & 3;

    if (hp) {
        float acc[MT][2][4];
#pragma unroll
        for (int mt = 0; mt < MT; mt++)
#pragma unroll
            for (int nj = 0; nj < 2; nj++)
#pragma unroll
                for (int r = 0; r < 4; r++) acc[mt][nj][r] = 0.f;

        const int NKT = H >> 5;
        float4 av[1];
        uint2 wh[4], wl[4];

        l_ldg<BM>(hp, ldh, whi, wlo, H, b0, j0, 0, tid, av, wh, wl);
        l_sts<BM>(buf0, tid, av, wh, wl);
        __syncthreads();
        l_ldg<BM>(hp, ldh, whi, wlo, H, b0, j0, 32, tid, av, wh, wl);

        for (int kt = 0; kt < NKT; kt += 2) {
            l_sts<BM>(buf1, tid, av, wh, wl);
            if (kt + 2 < NKT) l_ldg<BM>(hp, ldh, whi, wlo, H, b0, j0, (kt + 2) * 32, tid, av, wh, wl);
            l_compute<BM>(buf0, wn, gid, tig, acc);
            __syncthreads();
            if (kt + 2 < NKT) {
                l_sts<BM>(buf0, tid, av, wh, wl);
                if (kt + 3 < NKT) l_ldg<BM>(hp, ldh, whi, wlo, H, b0, j0, (kt + 3) * 32, tid, av, wh, wl);
            }
            l_compute<BM>(buf1, wn, gid, tig, acc);
            __syncthreads();
        }

        // gate exchange: EB[b_local][flat_col], stride 260 (floats)
        float* EB = (float*)sb;
#pragma unroll
        for (int mt = 0; mt < MT; mt++)
#pragma unroll
            for (int nj = 0; nj < 2; nj++) {
                int col = wn * 16 + nj * 8 + tig * 2;
                float* c = acc[mt][nj];
                EB[(mt * 16 + gid) * 260 + col]         = c[0];
                EB[(mt * 16 + gid) * 260 + col + 1]     = c[1];
                EB[(mt * 16 + gid + 8) * 260 + col]     = c[2];
                EB[(mt * 16 + gid + 8) * 260 + col + 1] = c[3];
            }
        __syncthreads();
    }

    const float* EB = (const float*)sb;
    const int jl = tid & 63;
    const int brow = tid >> 6;
#pragma unroll
    for (int i = 0; i < BM / 8; i++) {
        int bl_ = brow + i * 8;
        int b = b0 + bl_;
        const float* xr = Xg + (size_t)b * ldx;
        int j = j0 + jl;
        float a0 = 0.f, a1 = 0.f, a2 = 0.f, a3 = 0.f;
        if (hp) {
            a0 = EB[bl_ * 260 + jl];
            a1 = EB[bl_ * 260 + 64 + jl];
            a2 = EB[bl_ * 260 + 128 + jl];
            a3 = EB[bl_ * 260 + 192 + jl];
        }
        float gi = a0 + xr[j];
        float gf = a1 + xr[H + j];
        float gg = a2 + xr[2 * H + j];
        float go = a3 + xr[3 * H + j];
        float cpv = cp ? cp[(size_t)b * H + j] : 0.f;
        float cc = sigm(gf) * cpv + sigm(gi) * tanhf(gg);
        co[(size_t)b * H + j] = cc;
        ho[(size_t)b * ldo + j] = sigm(go) * tanhf(cc);
    }
}

template<int BM>
__global__ __launch_bounds__(512) void lstm_persist(PArgs pa, int H, int nsteps) {
    extern __shared__ unsigned lsb[];
    const PChain ch = pa.c[blockIdx.z];
    const int j0 = blockIdx.x * 64;
    const int b0 = blockIdx.y * BM;
    const int tid = threadIdx.x;
    const size_t CB = 512 * (size_t)H;

    for (int t = 0; t < nsteps; t++) {
        const float* Xg = ch.xg0 + (long)t * ch.dxg;
        const float* hp;
        const float* cp;
        int ldh;
        if (t == 0) { hp = ch.hp_init; cp = ch.cp_init; ldh = ch.ldh_init; }
        else {
            hp = ch.ho0 + (long)(t - 1) * ch.dho;
            cp = ch.cbuf + (size_t)(t & 1) * CB;
            ldh = ch.ldh;
        }
        float* ho = ch.ho0 + (long)t * ch.dho;
        float* co = ch.cbuf + (size_t)((t + 1) & 1) * CB;

        lstm_body<BM>(Xg, hp, cp, ch.whi, ch.wlo, ho, co,
                      ch.ldx, ldh, ch.ldo, H, lsb, j0, b0, tid);
        grid_barrier128();
    }
}

__global__ void build_h0c0(const float* __restrict__ CO, const float* __restrict__ TO,
                           const float* __restrict__ ccf, const float* __restrict__ ctf,
                           float* __restrict__ h0, float* __restrict__ c0) {
    int idx = blockIdx.x * blockDim.x + threadIdx.x;
    if (idx >= 512 * 512) return;
    int b = idx >> 9, j = idx & 511;
    float hv, cv;
    if (j < 256) { hv = CO[((size_t)b * 48 + 47) * 512 + j];        cv = ccf[b * 256 + j]; }
    else         { hv = TO[((size_t)b * 16 + 15) * 512 + (j - 256)]; cv = ctf[b * 256 + (j - 256)]; }
    h0[idx] = hv;
    c0[idx] = cv;
}

// ---------------------------------------------------------------------------
// Single-head attention, one block per batch element.
// ---------------------------------------------------------------------------
__global__ __launch_bounds__(256) void attn_kernel(
    const float* __restrict__ Q, const float* __restrict__ KV,
    float* __restrict__ O, int Lk)
{
    const int b = blockIdx.x;
    const int tid = threadIdx.x;
    __shared__ float Qs[48][68];
    __shared__ float Ks[48][68];
    __shared__ float s[48][48];

    const float* Qb = Q + (size_t)b * 48 * 512;
    const float* Kb = KV + (size_t)b * Lk * 1024;

    float acc[9];
#pragma unroll
    for (int i = 0; i < 9; i++) acc[i] = 0.f;

    for (int e0 = 0; e0 < 512; e0 += 64) {
        __syncthreads();
        for (int idx = tid; idx < 48 * 16; idx += 256) {
            int r = idx >> 4, cc = (idx & 15) << 2;
            *(float4*)&Qs[r][cc] = *(const float4*)(Qb + (size_t)r * 512 + e0 + cc);
        }
        for (int idx = tid; idx < Lk * 16; idx += 256) {
            int r = idx >> 4, cc = (idx & 15) << 2;
            *(float4*)&Ks[r][cc] = *(const float4*)(Kb + (size_t)r * 1024 + e0 + cc);
        }
        __syncthreads();
        int pi = 0;
        for (int idx = tid; idx < 48 * Lk; idx += 256, pi++) {
            int q = idx / Lk, k = idx - q * Lk;
            float sum = 0.f;
#pragma unroll 16
            for (int e = 0; e < 64; e++) sum += Qs[q][e] * Ks[k][e];
            acc[pi] += sum;
        }
    }
    __syncthreads();
    {
        const float scale = 0.04419417382415922f;   // 1/sqrt(512)
        int pi = 0;
        for (int idx = tid; idx < 48 * Lk; idx += 256, pi++) {
            int q = idx / Lk, k = idx - q * Lk;
            s[q][k] = acc[pi] * scale;
        }
    }
    __syncthreads();
    if (tid < 48) {
        float m = -1e30f;
        for (int k = 0; k < Lk; k++) m = fmaxf(m, s[tid][k]);
        float sum = 0.f;
        for (int k = 0; k < Lk; k++) { float e = expf(s[tid][k] - m); s[tid][k] = e; sum += e; }
        float inv = 1.f / sum;
        for (int k = 0; k < Lk; k++) s[tid][k] *= inv;
    }
    __syncthreads();

    float* Ob = O + (size_t)b * 48 * 512;
    const float* Vb = KV + (size_t)b * Lk * 1024 + 512;
    for (int e0 = 0; e0 < 512; e0 += 64) {
        for (int idx = tid; idx < Lk * 16; idx += 256) {
            int r = idx >> 4, cc = (idx & 15) << 2;
            *(float4*)&Ks[r][cc] = *(const float4*)(Vb + (size_t)r * 1024 + e0 + cc);
        }
        __syncthreads();
        for (int idx = tid; idx < 48 * 64; idx += 256) {
            int q = idx >> 6, e = idx & 63;
            float sum = 0.f;
            for (int k = 0; k < Lk; k++) sum += s[q][k] * Ks[k][e];
            Ob[(size_t)q * 512 + e0 + e] = sum;
        }
        __syncthreads();
    }
}

// ---------------------------------------------------------------------------
// Exact 1.5-entmax via warp bisection; one warp per row of 128.
// ---------------------------------------------------------------------------
__global__ __launch_bounds__(256) void entmax_kernel(
    const float* __restrict__ logits, float* __restrict__ out, int nrows)
{
    int row = blockIdx.x * 8 + (threadIdx.x >> 5);
    if (row >= nrows) return;
    int lane = threadIdx.x & 31;
    const float* x = logits + (size_t)row * 128;
    float z[4];
    float m = -1e30f;
#pragma unroll
    for (int i = 0; i < 4; i++) { z[i] = x[lane + 32 * i] * 0.5f; m = fmaxf(m, z[i]); }
#pragma unroll
    for (int o = 16; o; o >>= 1) m = fmaxf(m, __shfl_xor_sync(0xffffffffu, m, o));
#pragma unroll
    for (int i = 0; i < 4; i++) z[i] -= m;
    float lo = -1.f, hi = 0.f;
    for (int it = 0; it < 35; it++) {
        float tau = 0.5f * (lo + hi);
        float f = 0.f;
#pragma unroll
        for (int i = 0; i < 4; i++) { float d = fmaxf(z[i] - tau, 0.f); f += d * d; }
#pragma unroll
        for (int o = 16; o; o >>= 1) f += __shfl_xor_sync(0xffffffffu, f, o);
        if (f >= 1.f) lo = tau; else hi = tau;
    }
    float tau = 0.5f * (lo + hi);
    float* yo = out + (size_t)row * 128;
#pragma unroll
    for (int i = 0; i < 4; i++) { float d = fmaxf(z[i] - tau, 0.f); yo[lane + 32 * i] = d * d; }
}

// ---------------------------------------------------------------------------
extern "C" void kernel_launch(void* const* d_in, const int* in_sizes, int n_in,
                              void* d_out, int out_size) {
    const int*   li          = (const int*)  d_in[0];
    const float* char_seq    = (const float*)d_in[1];
    const float* tagset      = (const float*)d_in[2];
    const float* labels      = (const float*)d_in[3];
    const float* lang_embeds = (const float*)d_in[4];
    const float* c_w_ih_f    = (const float*)d_in[5];
    const float* c_w_hh_f    = (const float*)d_in[6];
    const float* c_b_f       = (const float*)d_in[7];
    const float* c_w_ih_b    = (const float*)d_in[8];
    const float* c_w_hh_b    = (const float*)d_in[9];
    const float* c_b_b       = (const float*)d_in[10];
    const float* t_w_ih_f    = (const float*)d_in[11];
    const float* t_w_hh_f    = (const float*)d_in[12];
    const float* t_b_f       = (const float*)d_in[13];
    const float* t_w_ih_b    = (const float*)d_in[14];
    const float* t_w_hh_b    = (const float*)d_in[15];
    const float* t_b_b       = (const float*)d_in[16];
    const float* cell_w_ih   = (const float*)d_in[17];
    const float* cell_w_hh   = (const float*)d_in[18];
    const float* cell_b      = (const float*)d_in[19];
    const float* ch_in_w     = (const float*)d_in[20];
    const float* ch_in_b     = (const float*)d_in[21];
    const float* ch_out_w    = (const float*)d_in[22];
    const float* ch_out_b    = (const float*)d_in[23];
    const float* tg_in_w     = (const float*)d_in[24];
    const float* tg_in_b     = (const float*)d_in[25];
    const float* tg_out_w    = (const float*)d_in[26];
    const float* tg_out_b    = (const float*)d_in[27];
    const float* fc_w        = (const float*)d_in[28];
    const float* fc_b        = (const float*)d_in[29];
    float* OUT = (float*)d_out;

    float* S = nullptr;
    cudaGetSymbolAddress((void**)&S, g_scratch);

    unsigned* WCF = (unsigned*)(S + O_WCF);
    unsigned* WCB = (unsigned*)(S + O_WCB);
    unsigned* WTF = (unsigned*)(S + O_WTF);
    unsigned* WTB = (unsigned*)(S + O_WTB);
    unsigned* WD  = (unsigned*)(S + O_WD);
    const int ENC_N2 = 131072;   // 1024 * 128
    const int DEC_N2 = 524288;   // 2048 * 256

    const int GSM = 98304;    // gemm_mma: 2 x 12288 words
    const int LSM = 110592;   // lstm_persist<32>: 2 x 13824 words
    static bool attr_set = false;
    if (!attr_set) {
        cudaFuncSetAttribute(gemm_mma, cudaFuncAttributeMaxDynamicSharedMemorySize, GSM);
        cudaFuncSetAttribute(lstm_persist<32>, cudaFuncAttributeMaxDynamicSharedMemorySize, LSM);
        attr_set = true;
    }

    // 1) input prep + weight pre-split
    prep_kernel<<<CDIV(5767168, 256), 256>>>(li, char_seq, tagset, lang_embeds,
                                             S + O_CS, S + O_TS);
    build_decin<<<CDIV(3145728, 256), 256>>>(labels, S + O_DECIN);
    wsplit_kernel<<<CDIV(ENC_N2, 256), 256>>>(c_w_hh_f, WCF, WCF + ENC_N2, ENC_N2);
    wsplit_kernel<<<CDIV(ENC_N2, 256), 256>>>(c_w_hh_b, WCB, WCB + ENC_N2, ENC_N2);
    wsplit_kernel<<<CDIV(ENC_N2, 256), 256>>>(t_w_hh_f, WTF, WTF + ENC_N2, ENC_N2);
    wsplit_kernel<<<CDIV(ENC_N2, 256), 256>>>(t_w_hh_b, WTB, WTB + ENC_N2, ENC_N2);
    wsplit_kernel<<<CDIV(DEC_N2, 256), 256>>>(cell_w_hh, WD, WD + DEC_N2, DEC_N2);

    // 2) input-projection GEMMs
    gemm_mma<<<dim3(8, 192), 512, GSM>>>(S + O_CS, c_w_ih_f, c_b_f, S + O_XCF, 24576, 1024, 192, 1024);
    gemm_mma<<<dim3(8, 192), 512, GSM>>>(S + O_CS, c_w_ih_b, c_b_b, S + O_XCB, 24576, 1024, 192, 1024);
    gemm_mma<<<dim3(8,  64), 512, GSM>>>(S + O_TS, t_w_ih_f, t_b_f, S + O_XTF,  8192, 1024, 128, 1024);
    gemm_mma<<<dim3(8,  64), 512, GSM>>>(S + O_TS, t_w_ih_b, t_b_b, S + O_XTB,  8192, 1024, 128, 1024);
    gemm_mma<<<dim3(16,192), 512, GSM>>>(S + O_DECIN, cell_w_ih, cell_b, S + O_XDEC, 24576, 2048, 128, 2048);

    // 3) encoder recurrences — persistent kernels (pre-split weights)
    {
        PArgs A;  // char: fwd + bwd, 48 steps, H=256, grid (4,16,2)=128 blocks
        A.c[0] = { S + O_XCF, 1024,
                   S + O_CO, 512,
                   nullptr, nullptr, WCF, WCF + ENC_N2, S + O_CCF,
                   48 * 1024, 48 * 512, 48 * 512, 0 };
        A.c[1] = { S + O_XCB + 47ll * 1024, -1024,
                   S + O_CO + 47ll * 512 + 256, -512,
                   nullptr, nullptr, WCB, WCB + ENC_N2, S + O_CCB,
                   48 * 1024, 48 * 512, 48 * 512, 0 };
        lstm_persist<32><<<dim3(4, 16, 2), 512, LSM>>>(A, 256, 48);

        PArgs T;  // tag: fwd + bwd, 16 steps, H=256
        T.c[0] = { S + O_XTF, 1024,
                   S + O_TO, 512,
                   nullptr, nullptr, WTF, WTF + ENC_N2, S + O_CTF,
                   16 * 1024, 16 * 512, 16 * 512, 0 };
        T.c[1] = { S + O_XTB + 15ll * 1024, -1024,
                   S + O_TO + 15ll * 512 + 256, -512,
                   nullptr, nullptr, WTB, WTB + ENC_N2, S + O_CTB,
                   16 * 1024, 16 * 512, 16 * 512, 0 };
        lstm_persist<32><<<dim3(4, 16, 2), 512, LSM>>>(T, 256, 16);
    }

    // 4) initial decoder state
    build_h0c0<<<1024, 256>>>(S + O_CO, S + O_TO, S + O_CCF, S + O_CTF,
                              S + O_H0, S + O_C0);

    // 5) decoder recurrence — persistent kernel, grid (8,16,1)=128 blocks
    {
        PArgs D;
        D.c[0] = { S + O_XDEC, 2048,
                   S + O_HS, 512,
                   S + O_H0, S + O_C0, WD, WD + DEC_N2, S + O_DC,
                   48 * 2048, 48 * 512, 48 * 512, 512 };
        D.c[1] = D.c[0];
        lstm_persist<32><<<dim3(8, 16, 1), 512, LSM>>>(D, 512, 48);
    }

    // 6) attention projections
    gemm_mma<<<dim3(4, 192), 512, GSM>>>(S + O_HS, ch_in_w, ch_in_b, S + O_QC, 24576, 512, 512, 512);
    gemm_mma<<<dim3(4, 192), 512, GSM>>>(S + O_HS, tg_in_w, tg_in_b, S + O_QT, 24576, 512, 512, 512);
    gemm_mma<<<dim3(8, 192), 512, GSM>>>(S + O_CO, ch_in_w + 512 * 512, ch_in_b + 512,
                                         S + O_KVC, 24576, 1024, 512, 1024);
    gemm_mma<<<dim3(8,  64), 512, GSM>>>(S + O_TO, tg_in_w + 512 * 512, tg_in_b + 512,
                                         S + O_KVT,  8192, 1024, 512, 1024);

    // 7) attention cores
    attn_kernel<<<512, 256>>>(S + O_QC, S + O_KVC, S + O_OC, 48);
    attn_kernel<<<512, 256>>>(S + O_QT, S + O_KVT, S + O_OT, 16);

    // 8) output projections straight into the concat buffer
    gemm_mma<<<dim3(4, 192), 512, GSM>>>(S + O_OC, ch_out_w, ch_out_b, S + O_CAT,       24576, 512, 512, 1024);
    gemm_mma<<<dim3(4, 192), 512, GSM>>>(S + O_OT, tg_out_w, tg_out_b, S + O_CAT + 512, 24576, 512, 512, 1024);

    // 9) final FC + entmax15
    gemm_mma<<<dim3(1, 192), 512, GSM>>>(S + O_CAT, fc_w, fc_b, S + O_LOG, 24576, 128, 1024, 128);
    entmax_kernel<<<3072, 256>>>(S + O_LOG, OUT, 24576);
}

// round 14
// speedup vs baseline: 1.0446x; 1.0446x over previous
#include <cuda_runtime.h>
#include <cuda_bf16.h>
#include <math.h>

#define CDIV(a,b) (((a)+(b)-1)/(b))

// Dimensions: B=512, SC=48, ST=16, E=512, H=256, N_CHARS=128, N_TAGS=64
constexpr size_t SZ(size_t n) { return (n + 255) & ~(size_t)255; }

constexpr size_t O_CS    = 0;                                    // [512,48,192]
constexpr size_t O_TS    = O_CS    + SZ(24576ull*192);           // [512,16,128]
constexpr size_t O_DECIN = O_TS    + SZ(8192ull*128);            // [512,48,128]
constexpr size_t O_XCF   = O_DECIN + SZ(24576ull*128);           // [512,48,1024]
constexpr size_t O_XCB   = O_XCF   + SZ(24576ull*1024);
constexpr size_t O_XTF   = O_XCB   + SZ(24576ull*1024);          // [512,16,1024]
constexpr size_t O_XTB   = O_XTF   + SZ(8192ull*1024);
constexpr size_t O_XDEC  = O_XTB   + SZ(8192ull*1024);           // [512,48,2048]
constexpr size_t O_CO    = O_XDEC  + SZ(24576ull*2048);          // [512,48,512]
constexpr size_t O_TO    = O_CO    + SZ(24576ull*512);           // [512,16,512]
constexpr size_t O_HS    = O_TO    + SZ(8192ull*512);            // [512,48,512]
constexpr size_t O_CCF   = O_HS    + SZ(24576ull*512);           // 2x[512,256]
constexpr size_t O_CCB   = O_CCF   + SZ(2ull*512*256);
constexpr size_t O_CTF   = O_CCB   + SZ(2ull*512*256);
constexpr size_t O_CTB   = O_CTF   + SZ(2ull*512*256);
constexpr size_t O_DC    = O_CTB   + SZ(2ull*512*256);           // 2x[512,512]
constexpr size_t O_H0    = O_DC    + SZ(2ull*512*512);
constexpr size_t O_C0    = O_H0    + SZ(512ull*512);
constexpr size_t O_QC    = O_C0    + SZ(512ull*512);             // [512,48,512]
constexpr size_t O_QT    = O_QC    + SZ(24576ull*512);
constexpr size_t O_KVC   = O_QT    + SZ(24576ull*512);           // [512,48,1024]
constexpr size_t O_KVT   = O_KVC   + SZ(24576ull*1024);          // [512,16,1024]
constexpr size_t O_OC    = O_KVT   + SZ(8192ull*1024);           // [512,48,512]
constexpr size_t O_OT    = O_OC    + SZ(24576ull*512);
constexpr size_t O_CAT   = O_OT    + SZ(24576ull*512);           // [24576,1024]
constexpr size_t O_LOG   = O_CAT   + SZ(24576ull*1024);          // [24576,128]
constexpr size_t O_END   = O_LOG   + SZ(24576ull*128);

__device__ float g_scratch[O_END];

// ---------------------------------------------------------------------------
// group-local barriers: one (cnt, gen) pair per (chain, b-tile) group, padded
// to 128B so no two groups share an L2 line. Max 64 groups.
// Each barrier returns cnt to 0 on completion, so reuse across launches with
// different group sizes is safe; gen grows monotonically (read-before-wait).
// ---------------------------------------------------------------------------
__device__ unsigned g_gcnt[64 * 32];
__device__ unsigned g_ggen[64 * 32];

__device__ __forceinline__ void group_barrier(int gid, unsigned nblk) {
    __syncthreads();
    __threadfence();
    if (threadIdx.x == 0) {
        volatile unsigned* vg = &g_ggen[gid * 32];
        unsigned my = *vg;
        if (atomicInc(&g_gcnt[gid * 32], nblk - 1u) == nblk - 1u) {
            atomicAdd(&g_ggen[gid * 32], 1u);
        } else {
            while (*vg == my) __nanosleep(32);
        }
    }
    __syncthreads();
}

// ---------------------------------------------------------------------------
__global__ void prep_kernel(const int* __restrict__ li,
                            const float* __restrict__ char_seq,
                            const float* __restrict__ tagset,
                            const float* __restrict__ lang_embeds,
                            float* __restrict__ cs, float* __restrict__ ts) {
    int idx = blockIdx.x * blockDim.x + threadIdx.x;
    const int n1 = 512 * 48 * 192;
    const int n2 = 512 * 16 * 128;
    if (idx < n1) {
        int b = idx / (48 * 192);
        int rem = idx - b * 48 * 192;
        int s = rem / 192, k = rem - s * 192;
        float v;
        if (k < 128) v = char_seq[(b * 48 + s) * 128 + k];
        else         v = lang_embeds[li[li[b]] * 64 + (k - 128)];
        cs[idx] = v;
    } else if (idx < n1 + n2) {
        int j = idx - n1;
        int b = j / (16 * 128);
        int rem = j - b * 16 * 128;
        int s = rem / 128, k = rem - s * 128;
        float v;
        if (k < 64) v = tagset[(b * 16 + s) * 64 + k];
        else        v = lang_embeds[li[li[b]] * 64 + (k - 64)];
        ts[j] = v;
    }
}

__global__ void build_decin(const float* __restrict__ labels, float* __restrict__ decin) {
    int idx = blockIdx.x * blockDim.x + threadIdx.x;
    if (idx >= 512 * 48 * 128) return;
    int t = (idx >> 7) % 48;
    decin[idx] = (t == 0) ? 0.f : labels[idx];
}

// ---------------------------------------------------------------------------
// bf16x3 helpers. x = hi + lo (both bf16): per-product error ~2^-18.
// D += Ah*Bh + Ah*Bl + Al*Bh with fp32 accumulate (m16n8k16).
// ---------------------------------------------------------------------------
__device__ __forceinline__ void split_bf(float x0, float x1,
                                         unsigned& hi2, unsigned& lo2) {
    unsigned h;
    asm("cvt.rn.bf16x2.f32 %0, %1, %2;" : "=r"(h) : "f"(x1), "f"(x0));
    float h0 = __uint_as_float(h << 16);
    float h1 = __uint_as_float(h & 0xffff0000u);
    float l0 = x0 - h0;
    float l1 = x1 - h1;
    unsigned l;
    asm("cvt.rn.bf16x2.f32 %0, %1, %2;" : "=r"(l) : "f"(l1), "f"(l0));
    hi2 = h; lo2 = l;
}

__device__ __forceinline__ void mma16bf(float* c, const unsigned* a, const unsigned* b) {
    asm volatile(
        "mma.sync.aligned.m16n8k16.row.col.f32.bf16.bf16.f32 "
        "{%0,%1,%2,%3}, {%4,%5,%6,%7}, {%8,%9}, {%0,%1,%2,%3};\n"
        : "+f"(c[0]), "+f"(c[1]), "+f"(c[2]), "+f"(c[3])
        : "r"(a[0]), "r"(a[1]), "r"(a[2]), "r"(a[3]), "r"(b[0]), "r"(b[1]));
}

// k2 permutation within each 8-word group so the fragment pair (k2, k2+4)
// is one LDS.64: pos = group*8 + (k2&3)*2 + ((k2>>2)&1)
__device__ __forceinline__ int permk2(int k2) {
    return (k2 >> 3) * 8 + (k2 & 3) * 2 + ((k2 >> 2) & 1);
}

// ---------------------------------------------------------------------------
// GEMM: C[m,n] = sum_k A[m,k]*W[n,k] + bias[n]. 128x128 tile, k-step 32,
// double-buffered, 512 threads = 16 warps (4m x 4n), warp tile 32x32.
// smem (uint32 words): Ah[128*24] Al Bh Bl; rows stride 24 words.
// Stage = 12288 words; double buffer = 98304 bytes.
// ---------------------------------------------------------------------------
__device__ __forceinline__ void g_ldg(const float* __restrict__ A,
                                      const float* __restrict__ W,
                                      int K, int bm, int bn, int k0, int tid,
                                      float4* av, float4* wv) {
#pragma unroll
    for (int i = 0; i < 2; i++) {
        int idx = tid + i * 512;
        int row = idx >> 3, fc = idx & 7;
        av[i] = *(const float4*)(A + (size_t)(bm + row) * K + k0 + fc * 4);
        wv[i] = *(const float4*)(W + (size_t)(bn + row) * K + k0 + fc * 4);
    }
}

__device__ __forceinline__ void g_sts(unsigned* __restrict__ buf, int tid,
                                      const float4* av, const float4* wv) {
    unsigned* Ah = buf;
    unsigned* Al = buf + 3072;
    unsigned* Bh = buf + 6144;
    unsigned* Bl = buf + 9216;
#pragma unroll
    for (int i = 0; i < 2; i++) {
        int idx = tid + i * 512;
        int row = idx >> 3, fc = idx & 7;
        int pa = row * 24 + permk2(fc * 2);
        int pb = row * 24 + permk2(fc * 2 + 1);
        unsigned h, l;
        split_bf(av[i].x, av[i].y, h, l); Ah[pa] = h; Al[pa] = l;
        split_bf(av[i].z, av[i].w, h, l); Ah[pb] = h; Al[pb] = l;
        split_bf(wv[i].x, wv[i].y, h, l); Bh[pa] = h; Bl[pa] = l;
        split_bf(wv[i].z, wv[i].w, h, l); Bh[pb] = h; Bl[pb] = l;
    }
}

__device__ __forceinline__ void g_compute(const unsigned* __restrict__ buf,
                                          int wm, int wn, int gid, int tig,
                                          float (&acc)[2][4][4]) {
    const unsigned* Ah = buf;
    const unsigned* Al = buf + 3072;
    const unsigned* Bh = buf + 6144;
    const unsigned* Bl = buf + 9216;
#pragma unroll
    for (int s = 0; s < 2; s++) {
        unsigned ah[2][4], al[2][4];
#pragma unroll
        for (int mt = 0; mt < 2; mt++) {
            int o = (wm * 32 + mt * 16 + gid) * 24 + s * 8 + tig * 2;
            uint2 p = *(const uint2*)(Ah + o);
            uint2 q = *(const uint2*)(Ah + o + 192);   // +8 rows
            ah[mt][0] = p.x; ah[mt][2] = p.y; ah[mt][1] = q.x; ah[mt][3] = q.y;
            uint2 r = *(const uint2*)(Al + o);
            uint2 t = *(const uint2*)(Al + o + 192);
            al[mt][0] = r.x; al[mt][2] = r.y; al[mt][1] = t.x; al[mt][3] = t.y;
        }
        unsigned bh[4][2], bl[4][2];
#pragma unroll
        for (int j = 0; j < 4; j++) {
            int o = (wn * 32 + j * 8 + gid) * 24 + s * 8 + tig * 2;
            uint2 p = *(const uint2*)(Bh + o);
            bh[j][0] = p.x; bh[j][1] = p.y;
            uint2 q = *(const uint2*)(Bl + o);
            bl[j][0] = q.x; bl[j][1] = q.y;
        }
#pragma unroll
        for (int mt = 0; mt < 2; mt++)
#pragma unroll
            for (int j = 0; j < 4; j++) {
                float* c = acc[mt][j];
                mma16bf(c, ah[mt], bh[j]);
                mma16bf(c, ah[mt], bl[j]);
                mma16bf(c, al[mt], bh[j]);
            }
    }
}

__global__ __launch_bounds__(512) void gemm_mma(
    const float* __restrict__ A, const float* __restrict__ W,
    const float* __restrict__ bias, float* __restrict__ C,
    int M, int N, int K, int ldc)
{
    extern __shared__ unsigned gsb[];
    unsigned* buf0 = gsb;
    unsigned* buf1 = gsb + 12288;
    const int bm = blockIdx.y * 128;
    const int bn = blockIdx.x * 128;
    const int tid = threadIdx.x;
    const int wid = tid >> 5, lane = tid & 31;
    const int wm = wid >> 2, wn = wid & 3;
    const int gid = lane >> 2, tig = lane & 3;

    float acc[2][4][4];
#pragma unroll
    for (int i = 0; i < 2; i++)
#pragma unroll
        for (int j = 0; j < 4; j++)
#pragma unroll
            for (int r = 0; r < 4; r++) acc[i][j][r] = 0.f;

    const int NT = K >> 5;
    float4 av[2], wv[2];

    g_ldg(A, W, K, bm, bn, 0, tid, av, wv);
    g_sts(buf0, tid, av, wv);
    __syncthreads();
    g_ldg(A, W, K, bm, bn, 32, tid, av, wv);

    for (int kt = 0; kt < NT; kt += 2) {
        g_sts(buf1, tid, av, wv);
        if (kt + 2 < NT) g_ldg(A, W, K, bm, bn, (kt + 2) * 32, tid, av, wv);
        g_compute(buf0, wm, wn, gid, tig, acc);
        __syncthreads();
        if (kt + 2 < NT) {
            g_sts(buf0, tid, av, wv);
            if (kt + 3 < NT) g_ldg(A, W, K, bm, bn, (kt + 3) * 32, tid, av, wv);
        }
        g_compute(buf1, wm, wn, gid, tig, acc);
        __syncthreads();
    }

#pragma unroll
    for (int mt = 0; mt < 2; mt++)
#pragma unroll
        for (int nt = 0; nt < 4; nt++) {
            int row = bm + wm * 32 + mt * 16 + gid;
            int col = bn + wn * 32 + nt * 8 + tig * 2;
            float b0 = bias[col], b1 = bias[col + 1];
            float* c = acc[mt][nt];
            float* p0 = C + (size_t)row * ldc + col;
            float* p1 = C + (size_t)(row + 8) * ldc + col;
            p0[0] = c[0] + b0; p0[1] = c[1] + b1;
            p1[0] = c[2] + b0; p1[1] = c[3] + b1;
        }
}

// ---------------------------------------------------------------------------
// Persistent tensor-core LSTM (bf16x3) with GROUP-LOCAL barriers.
// 128 blocks x 512 threads, 1 block/SM. Dependency analysis: block (jx,by,z)
// reads h rows [by*BM, by*BM+BM) written only by blocks (*,by,z); c state is
// block-private. So each step only needs a barrier among the gridDim.x
// blocks sharing (by,z) — group id = z*gridDim.y + by.
// Block tile: BM batch x 64 j x 4 gates (N=256), 16 warps, each warp N=16.
// smem stage (words): Ah[BM*24] Al[BM*24] Bh[256*24] Bl[256*24] = 13824;
// double buffer = 110592 bytes. Epilogue reuses smem as float EB[BM][260].
// ---------------------------------------------------------------------------
struct PChain {
    const float* xg0;  long dxg;      // Xg(t) = xg0 + t*dxg
    float*       ho0;  long dho;      // ho(t) = ho0 + t*dho; hp(t)=ho(t-1)
    const float* hp_init;             // t==0 h (nullptr => zeros)
    const float* cp_init;             // t==0 c (nullptr => zeros)
    const float* whh;                 // [4H,H]
    float*       cbuf;                // 2 x [512,H] ping-pong
    int ldx, ldh, ldo, ldh_init;
};
struct PArgs { PChain c[2]; };

__device__ __forceinline__ float sigm(float x) { return 1.f / (1.f + expf(-x)); }

template<int BM>
__device__ __forceinline__ void l_ldg(const float* hp, int ldh, const float* whh,
                                      int H, int b0, int j0, int k0, int tid,
                                      float4* av, float4* wv) {
    if (tid < BM * 8) {
        int r = tid >> 3, fc = tid & 7;
        av[0] = *(const float4*)(hp + (size_t)(b0 + r) * ldh + k0 + fc * 4);
    }
#pragma unroll
    for (int i = 0; i < 4; i++) {
        int idx = tid + i * 512;
        int r = idx >> 3, fc = idx & 7;
        int g = r >> 6, jl = r & 63;
        wv[i] = *(const float4*)(whh + (size_t)(g * H + j0 + jl) * H + k0 + fc * 4);
    }
}

template<int BM>
__device__ __forceinline__ void l_sts(unsigned* __restrict__ buf, int tid,
                                      const float4* av, const float4* wv) {
    unsigned* Ah = buf;
    unsigned* Al = buf + BM * 24;
    unsigned* Bh = buf + 2 * BM * 24;
    unsigned* Bl = buf + 2 * BM * 24 + 6144;
    if (tid < BM * 8) {
        int r = tid >> 3, fc = tid & 7;
        int pa = r * 24 + permk2(fc * 2);
        int pb = r * 24 + permk2(fc * 2 + 1);
        unsigned h, l;
        split_bf(av[0].x, av[0].y, h, l); Ah[pa] = h; Al[pa] = l;
        split_bf(av[0].z, av[0].w, h, l); Ah[pb] = h; Al[pb] = l;
    }
#pragma unroll
    for (int i = 0; i < 4; i++) {
        int idx = tid + i * 512;
        int r = idx >> 3, fc = idx & 7;
        int pa = r * 24 + permk2(fc * 2);
        int pb = r * 24 + permk2(fc * 2 + 1);
        unsigned h, l;
        split_bf(wv[i].x, wv[i].y, h, l); Bh[pa] = h; Bl[pa] = l;
        split_bf(wv[i].z, wv[i].w, h, l); Bh[pb] = h; Bl[pb] = l;
    }
}

template<int BM>
__device__ __forceinline__ void l_compute(const unsigned* __restrict__ buf,
                                          int wn, int gid, int tig,
                                          float (&acc)[BM/16][2][4]) {
    constexpr int MT = BM / 16;
    const unsigned* Ah = buf;
    const unsigned* Al = buf + BM * 24;
    const unsigned* Bh = buf + 2 * BM * 24;
    const unsigned* Bl = buf + 2 * BM * 24 + 6144;
#pragma unroll
    for (int s = 0; s < 2; s++) {
        unsigned ah[MT][4], al[MT][4];
#pragma unroll
        for (int mt = 0; mt < MT; mt++) {
            int o = (mt * 16 + gid) * 24 + s * 8 + tig * 2;
            uint2 p = *(const uint2*)(Ah + o);
            uint2 q = *(const uint2*)(Ah + o + 192);
            ah[mt][0] = p.x; ah[mt][2] = p.y; ah[mt][1] = q.x; ah[mt][3] = q.y;
            uint2 r = *(const uint2*)(Al + o);
            uint2 t = *(const uint2*)(Al + o + 192);
            al[mt][0] = r.x; al[mt][2] = r.y; al[mt][1] = t.x; al[mt][3] = t.y;
        }
        unsigned bh[2][2], bl[2][2];
#pragma unroll
        for (int nj = 0; nj < 2; nj++) {
            int o = (wn * 16 + nj * 8 + gid) * 24 + s * 8 + tig * 2;
            uint2 p = *(const uint2*)(Bh + o);
            bh[nj][0] = p.x; bh[nj][1] = p.y;
            uint2 q = *(const uint2*)(Bl + o);
            bl[nj][0] = q.x; bl[nj][1] = q.y;
        }
#pragma unroll
        for (int mt = 0; mt < MT; mt++)
#pragma unroll
            for (int nj = 0; nj < 2; nj++) {
                float* c = acc[mt][nj];
                mma16bf(c, ah[mt], bh[nj]);
                mma16bf(c, ah[mt], bl[nj]);
                mma16bf(c, al[mt], bh[nj]);
            }
    }
}

template<int BM>
__device__ void lstm_body(const float* Xg, const float* hp, const float* cp,
                          const float* whh, float* ho, float* co,
                          int ldx, int ldh, int ldo, int H,
                          unsigned* sb, int j0, int b0, int tid) {
    constexpr int MT = BM / 16;
    constexpr int BUFSZ = (2 * BM + 512) * 24;   // 13824 for BM=32
    unsigned* buf0 = sb;
    unsigned* buf1 = sb + BUFSZ;
    const int lane = tid & 31;
    const int wn = tid >> 5;
    const int gid = lane >> 2, tig = lane & 3;

    if (hp) {
        float acc[MT][2][4];
#pragma unroll
        for (int mt = 0; mt < MT; mt++)
#pragma unroll
            for (int nj = 0; nj < 2; nj++)
#pragma unroll
                for (int r = 0; r < 4; r++) acc[mt][nj][r] = 0.f;

        const int NKT = H >> 5;
        float4 av[1], wv[4];

        l_ldg<BM>(hp, ldh, whh, H, b0, j0, 0, tid, av, wv);
        l_sts<BM>(buf0, tid, av, wv);
        __syncthreads();
        l_ldg<BM>(hp, ldh, whh, H, b0, j0, 32, tid, av, wv);

        for (int kt = 0; kt < NKT; kt += 2) {
            l_sts<BM>(buf1, tid, av, wv);
            if (kt + 2 < NKT) l_ldg<BM>(hp, ldh, whh, H, b0, j0, (kt + 2) * 32, tid, av, wv);
            l_compute<BM>(buf0, wn, gid, tig, acc);
            __syncthreads();
            if (kt + 2 < NKT) {
                l_sts<BM>(buf0, tid, av, wv);
                if (kt + 3 < NKT) l_ldg<BM>(hp, ldh, whh, H, b0, j0, (kt + 3) * 32, tid, av, wv);
            }
            l_compute<BM>(buf1, wn, gid, tig, acc);
            __syncthreads();
        }

        // gate exchange: EB[b_local][flat_col], stride 260 (floats)
        float* EB = (float*)sb;
#pragma unroll
        for (int mt = 0; mt < MT; mt++)
#pragma unroll
            for (int nj = 0; nj < 2; nj++) {
                int col = wn * 16 + nj * 8 + tig * 2;
                float* c = acc[mt][nj];
                EB[(mt * 16 + gid) * 260 + col]         = c[0];
                EB[(mt * 16 + gid) * 260 + col + 1]     = c[1];
                EB[(mt * 16 + gid + 8) * 260 + col]     = c[2];
                EB[(mt * 16 + gid + 8) * 260 + col + 1] = c[3];
            }
        __syncthreads();
    }

    const float* EB = (const float*)sb;
    const int jl = tid & 63;
    const int brow = tid >> 6;
#pragma unroll
    for (int i = 0; i < BM / 8; i++) {
        int bl_ = brow + i * 8;
        int b = b0 + bl_;
        const float* xr = Xg + (size_t)b * ldx;
        int j = j0 + jl;
        float a0 = 0.f, a1 = 0.f, a2 = 0.f, a3 = 0.f;
        if (hp) {
            a0 = EB[bl_ * 260 + jl];
            a1 = EB[bl_ * 260 + 64 + jl];
            a2 = EB[bl_ * 260 + 128 + jl];
            a3 = EB[bl_ * 260 + 192 + jl];
        }
        float gi = a0 + xr[j];
        float gf = a1 + xr[H + j];
        float gg = a2 + xr[2 * H + j];
        float go = a3 + xr[3 * H + j];
        float cpv = cp ? cp[(size_t)b * H + j] : 0.f;
        float cc = sigm(gf) * cpv + sigm(gi) * tanhf(gg);
        co[(size_t)b * H + j] = cc;
        ho[(size_t)b * ldo + j] = sigm(go) * tanhf(cc);
    }
}

template<int BM>
__global__ __launch_bounds__(512) void lstm_persist(PArgs pa, int H, int nsteps) {
    extern __shared__ unsigned lsb[];
    const PChain ch = pa.c[blockIdx.z];
    const int j0 = blockIdx.x * 64;
    const int b0 = blockIdx.y * BM;
    const int tid = threadIdx.x;
    const size_t CB = 512 * (size_t)H;
    const int grp = blockIdx.z * gridDim.y + blockIdx.y;   // group id
    const unsigned nblk = gridDim.x;                       // blocks per group

    for (int t = 0; t < nsteps; t++) {
        const float* Xg = ch.xg0 + (long)t * ch.dxg;
        const float* hp;
        const float* cp;
        int ldh;
        if (t == 0) { hp = ch.hp_init; cp = ch.cp_init; ldh = ch.ldh_init; }
        else {
            hp = ch.ho0 + (long)(t - 1) * ch.dho;
            cp = ch.cbuf + (size_t)(t & 1) * CB;
            ldh = ch.ldh;
        }
        float* ho = ch.ho0 + (long)t * ch.dho;
        float* co = ch.cbuf + (size_t)((t + 1) & 1) * CB;

        lstm_body<BM>(Xg, hp, cp, ch.whh, ho, co,
                      ch.ldx, ldh, ch.ldo, H, lsb, j0, b0, tid);
        if (t + 1 < nsteps) group_barrier(grp, nblk);
    }
}

__global__ void build_h0c0(const float* __restrict__ CO, const float* __restrict__ TO,
                           const float* __restrict__ ccf, const float* __restrict__ ctf,
                           float* __restrict__ h0, float* __restrict__ c0) {
    int idx = blockIdx.x * blockDim.x + threadIdx.x;
    if (idx >= 512 * 512) return;
    int b = idx >> 9, j = idx & 511;
    float hv, cv;
    if (j < 256) { hv = CO[((size_t)b * 48 + 47) * 512 + j];        cv = ccf[b * 256 + j]; }
    else         { hv = TO[((size_t)b * 16 + 15) * 512 + (j - 256)]; cv = ctf[b * 256 + (j - 256)]; }
    h0[idx] = hv;
    c0[idx] = cv;
}

// ---------------------------------------------------------------------------
// Single-head attention, one block per batch element.
// ---------------------------------------------------------------------------
__global__ __launch_bounds__(256) void attn_kernel(
    const float* __restrict__ Q, const float* __restrict__ KV,
    float* __restrict__ O, int Lk)
{
    const int b = blockIdx.x;
    const int tid = threadIdx.x;
    __shared__ float Qs[48][68];
    __shared__ float Ks[48][68];
    __shared__ float s[48][48];

    const float* Qb = Q + (size_t)b * 48 * 512;
    const float* Kb = KV + (size_t)b * Lk * 1024;

    float acc[9];
#pragma unroll
    for (int i = 0; i < 9; i++) acc[i] = 0.f;

    for (int e0 = 0; e0 < 512; e0 += 64) {
        __syncthreads();
        for (int idx = tid; idx < 48 * 16; idx += 256) {
            int r = idx >> 4, cc = (idx & 15) << 2;
            *(float4*)&Qs[r][cc] = *(const float4*)(Qb + (size_t)r * 512 + e0 + cc);
        }
        for (int idx = tid; idx < Lk * 16; idx += 256) {
            int r = idx >> 4, cc = (idx & 15) << 2;
            *(float4*)&Ks[r][cc] = *(const float4*)(Kb + (size_t)r * 1024 + e0 + cc);
        }
        __syncthreads();
        int pi = 0;
        for (int idx = tid; idx < 48 * Lk; idx += 256, pi++) {
            int q = idx / Lk, k = idx - q * Lk;
            float sum = 0.f;
#pragma unroll 16
            for (int e = 0; e < 64; e++) sum += Qs[q][e] * Ks[k][e];
            acc[pi] += sum;
        }
    }
    __syncthreads();
    {
        const float scale = 0.04419417382415922f;   // 1/sqrt(512)
        int pi = 0;
        for (int idx = tid; idx < 48 * Lk; idx += 256, pi++) {
            int q = idx / Lk, k = idx - q * Lk;
            s[q][k] = acc[pi] * scale;
        }
    }
    __syncthreads();
    if (tid < 48) {
        float m = -1e30f;
        for (int k = 0; k < Lk; k++) m = fmaxf(m, s[tid][k]);
        float sum = 0.f;
        for (int k = 0; k < Lk; k++) { float e = expf(s[tid][k] - m); s[tid][k] = e; sum += e; }
        float inv = 1.f / sum;
        for (int k = 0; k < Lk; k++) s[tid][k] *= inv;
    }
    __syncthreads();

    float* Ob = O + (size_t)b * 48 * 512;
    const float* Vb = KV + (size_t)b * Lk * 1024 + 512;
    for (int e0 = 0; e0 < 512; e0 += 64) {
        for (int idx = tid; idx < Lk * 16; idx += 256) {
            int r = idx >> 4, cc = (idx & 15) << 2;
            *(float4*)&Ks[r][cc] = *(const float4*)(Vb + (size_t)r * 1024 + e0 + cc);
        }
        __syncthreads();
        for (int idx = tid; idx < 48 * 64; idx += 256) {
            int q = idx >> 6, e = idx & 63;
            float sum = 0.f;
            for (int k = 0; k < Lk; k++) sum += s[q][k] * Ks[k][e];
            Ob[(size_t)q * 512 + e0 + e] = sum;
        }
        __syncthreads();
    }
}

// ---------------------------------------------------------------------------
// Exact 1.5-entmax via warp bisection; one warp per row of 128.
// ---------------------------------------------------------------------------
__global__ __launch_bounds__(256) void entmax_kernel(
    const float* __restrict__ logits, float* __restrict__ out, int nrows)
{
    int row = blockIdx.x * 8 + (threadIdx.x >> 5);
    if (row >= nrows) return;
    int lane = threadIdx.x & 31;
    const float* x = logits + (size_t)row * 128;
    float z[4];
    float m = -1e30f;
#pragma unroll
    for (int i = 0; i < 4; i++) { z[i] = x[lane + 32 * i] * 0.5f; m = fmaxf(m, z[i]); }
#pragma unroll
    for (int o = 16; o; o >>= 1) m = fmaxf(m, __shfl_xor_sync(0xffffffffu, m, o));
#pragma unroll
    for (int i = 0; i < 4; i++) z[i] -= m;
    float lo = -1.f, hi = 0.f;
    for (int it = 0; it < 35; it++) {
        float tau = 0.5f * (lo + hi);
        float f = 0.f;
#pragma unroll
        for (int i = 0; i < 4; i++) { float d = fmaxf(z[i] - tau, 0.f); f += d * d; }
#pragma unroll
        for (int o = 16; o; o >>= 1) f += __shfl_xor_sync(0xffffffffu, f, o);
        if (f >= 1.f) lo = tau; else hi = tau;
    }
    float tau = 0.5f * (lo + hi);
    float* yo = out + (size_t)row * 128;
#pragma unroll
    for (int i = 0; i < 4; i++) { float d = fmaxf(z[i] - tau, 0.f); yo[lane + 32 * i] = d * d; }
}

// ---------------------------------------------------------------------------
extern "C" void kernel_launch(void* const* d_in, const int* in_sizes, int n_in,
                              void* d_out, int out_size) {
    const int*   li          = (const int*)  d_in[0];
    const float* char_seq    = (const float*)d_in[1];
    const float* tagset      = (const float*)d_in[2];
    const float* labels      = (const float*)d_in[3];
    const float* lang_embeds = (const float*)d_in[4];
    const float* c_w_ih_f    = (const float*)d_in[5];
    const float* c_w_hh_f    = (const float*)d_in[6];
    const float* c_b_f       = (const float*)d_in[7];
    const float* c_w_ih_b    = (const float*)d_in[8];
    const float* c_w_hh_b    = (const float*)d_in[9];
    const float* c_b_b       = (const float*)d_in[10];
    const float* t_w_ih_f    = (const float*)d_in[11];
    const float* t_w_hh_f    = (const float*)d_in[12];
    const float* t_b_f       = (const float*)d_in[13];
    const float* t_w_ih_b    = (const float*)d_in[14];
    const float* t_w_hh_b    = (const float*)d_in[15];
    const float* t_b_b       = (const float*)d_in[16];
    const float* cell_w_ih   = (const float*)d_in[17];
    const float* cell_w_hh   = (const float*)d_in[18];
    const float* cell_b      = (const float*)d_in[19];
    const float* ch_in_w     = (const float*)d_in[20];
    const float* ch_in_b     = (const float*)d_in[21];
    const float* ch_out_w    = (const float*)d_in[22];
    const float* ch_out_b    = (const float*)d_in[23];
    const float* tg_in_w     = (const float*)d_in[24];
    const float* tg_in_b     = (const float*)d_in[25];
    const float* tg_out_w    = (const float*)d_in[26];
    const float* tg_out_b    = (const float*)d_in[27];
    const float* fc_w        = (const float*)d_in[28];
    const float* fc_b        = (const float*)d_in[29];
    float* OUT = (float*)d_out;

    float* S = nullptr;
    cudaGetSymbolAddress((void**)&S, g_scratch);

    const int GSM = 98304;    // gemm_mma: 2 x 12288 words
    const int LSM = 110592;   // lstm_persist<32>: 2 x 13824 words
    static bool attr_set = false;
    if (!attr_set) {
        cudaFuncSetAttribute(gemm_mma, cudaFuncAttributeMaxDynamicSharedMemorySize, GSM);
        cudaFuncSetAttribute(lstm_persist<32>, cudaFuncAttributeMaxDynamicSharedMemorySize, LSM);
        attr_set = true;
    }

    // 1) input prep
    prep_kernel<<<CDIV(5767168, 256), 256>>>(li, char_seq, tagset, lang_embeds,
                                             S + O_CS, S + O_TS);
    build_decin<<<CDIV(3145728, 256), 256>>>(labels, S + O_DECIN);

    // 2) input-projection GEMMs
    gemm_mma<<<dim3(8, 192), 512, GSM>>>(S + O_CS, c_w_ih_f, c_b_f, S + O_XCF, 24576, 1024, 192, 1024);
    gemm_mma<<<dim3(8, 192), 512, GSM>>>(S + O_CS, c_w_ih_b, c_b_b, S + O_XCB, 24576, 1024, 192, 1024);
    gemm_mma<<<dim3(8,  64), 512, GSM>>>(S + O_TS, t_w_ih_f, t_b_f, S + O_XTF,  8192, 1024, 128, 1024);
    gemm_mma<<<dim3(8,  64), 512, GSM>>>(S + O_TS, t_w_ih_b, t_b_b, S + O_XTB,  8192, 1024, 128, 1024);
    gemm_mma<<<dim3(16,192), 512, GSM>>>(S + O_DECIN, cell_w_ih, cell_b, S + O_XDEC, 24576, 2048, 128, 2048);

    // 3) encoder recurrences — persistent kernels, group-local barriers
    {
        PArgs A;  // char: fwd + bwd, 48 steps, H=256, grid (4,16,2)=128 blocks
        A.c[0] = { S + O_XCF, 1024,
                   S + O_CO, 512,
                   nullptr, nullptr, c_w_hh_f, S + O_CCF,
                   48 * 1024, 48 * 512, 48 * 512, 0 };
        A.c[1] = { S + O_XCB + 47ll * 1024, -1024,
                   S + O_CO + 47ll * 512 + 256, -512,
                   nullptr, nullptr, c_w_hh_b, S + O_CCB,
                   48 * 1024, 48 * 512, 48 * 512, 0 };
        lstm_persist<32><<<dim3(4, 16, 2), 512, LSM>>>(A, 256, 48);

        PArgs T;  // tag: fwd + bwd, 16 steps, H=256
        T.c[0] = { S + O_XTF, 1024,
                   S + O_TO, 512,
                   nullptr, nullptr, t_w_hh_f, S + O_CTF,
                   16 * 1024, 16 * 512, 16 * 512, 0 };
        T.c[1] = { S + O_XTB + 15ll * 1024, -1024,
                   S + O_TO + 15ll * 512 + 256, -512,
                   nullptr, nullptr, t_w_hh_b, S + O_CTB,
                   16 * 1024, 16 * 512, 16 * 512, 0 };
        lstm_persist<32><<<dim3(4, 16, 2), 512, LSM>>>(T, 256, 16);
    }

    // 4) initial decoder state
    build_h0c0<<<1024, 256>>>(S + O_CO, S + O_TO, S + O_CCF, S + O_CTF,
                              S + O_H0, S + O_C0);

    // 5) decoder recurrence — persistent kernel, grid (8,16,1)=128 blocks
    {
        PArgs D;
        D.c[0] = { S + O_XDEC, 2048,
                   S + O_HS, 512,
                   S + O_H0, S + O_C0, cell_w_hh, S + O_DC,
                   48 * 2048, 48 * 512, 48 * 512, 512 };
        D.c[1] = D.c[0];
        lstm_persist<32><<<dim3(8, 16, 1), 512, LSM>>>(D, 512, 48);
    }

    // 6) attention projections
    gemm_mma<<<dim3(4, 192), 512, GSM>>>(S + O_HS, ch_in_w, ch_in_b, S + O_QC, 24576, 512, 512, 512);
    gemm_mma<<<dim3(4, 192), 512, GSM>>>(S + O_HS, tg_in_w, tg_in_b, S + O_QT, 24576, 512, 512, 512);
    gemm_mma<<<dim3(8, 192), 512, GSM>>>(S + O_CO, ch_in_w + 512 * 512, ch_in_b + 512,
                                         S + O_KVC, 24576, 1024, 512, 1024);
    gemm_mma<<<dim3(8,  64), 512, GSM>>>(S + O_TO, tg_in_w + 512 * 512, tg_in_b + 512,
                                         S + O_KVT,  8192, 1024, 512, 1024);

    // 7) attention cores
    attn_kernel<<<512, 256>>>(S + O_QC, S + O_KVC, S + O_OC, 48);
    attn_kernel<<<512, 256>>>(S + O_QT, S + O_KVT, S + O_OT, 16);

    // 8) output projections straight into the concat buffer
    gemm_mma<<<dim3(4, 192), 512, GSM>>>(S + O_OC, ch_out_w, ch_out_b, S + O_CAT,       24576, 512, 512, 1024);
    gemm_mma<<<dim3(4, 192), 512, GSM>>>(S + O_OT, tg_out_w, tg_out_b, S + O_CAT + 512, 24576, 512, 512, 1024);

    // 9) final FC + entmax15
    gemm_mma<<<dim3(1, 192), 512, GSM>>>(S + O_CAT, fc_w, fc_b, S + O_LOG, 24576, 128, 1024, 128);
    entmax_kernel<<<3072, 256>>>(S + O_LOG, OUT, 24576);
}

// round 15
// speedup vs baseline: 1.0509x; 1.0060x over previous
#include <cuda_runtime.h>
#include <cuda_bf16.h>
#include <math.h>

#define CDIV(a,b) (((a)+(b)-1)/(b))

// Dimensions: B=512, SC=48, ST=16, E=512, H=256, N_CHARS=128, N_TAGS=64
constexpr size_t SZ(size_t n) { return (n + 255) & ~(size_t)255; }

constexpr size_t O_CS    = 0;                                    // [512,48,192]
constexpr size_t O_TS    = O_CS    + SZ(24576ull*192);           // [512,16,128]
constexpr size_t O_DECIN = O_TS    + SZ(8192ull*128);            // [512,48,128]
constexpr size_t O_XCF   = O_DECIN + SZ(24576ull*128);           // [512,48,1024]
constexpr size_t O_XCB   = O_XCF   + SZ(24576ull*1024);
constexpr size_t O_XTF   = O_XCB   + SZ(24576ull*1024);          // [512,16,1024]
constexpr size_t O_XTB   = O_XTF   + SZ(8192ull*1024);
constexpr size_t O_XDEC  = O_XTB   + SZ(8192ull*1024);           // [512,48,2048]
constexpr size_t O_CO    = O_XDEC  + SZ(24576ull*2048);          // [512,48,512]
constexpr size_t O_TO    = O_CO    + SZ(24576ull*512);           // [512,16,512]
constexpr size_t O_HS    = O_TO    + SZ(8192ull*512);            // [512,48,512]
constexpr size_t O_CCF   = O_HS    + SZ(24576ull*512);           // 2x[512,256]
constexpr size_t O_CCB   = O_CCF   + SZ(2ull*512*256);
constexpr size_t O_CTF   = O_CCB   + SZ(2ull*512*256);
constexpr size_t O_CTB   = O_CTF   + SZ(2ull*512*256);
constexpr size_t O_DC    = O_CTB   + SZ(2ull*512*256);           // 2x[512,512]
constexpr size_t O_H0    = O_DC    + SZ(2ull*512*512);
constexpr size_t O_C0    = O_H0    + SZ(512ull*512);
constexpr size_t O_QC    = O_C0    + SZ(512ull*512);             // [512,48,512]
constexpr size_t O_QT    = O_QC    + SZ(24576ull*512);
constexpr size_t O_KVC   = O_QT    + SZ(24576ull*512);           // [512,48,1024]
constexpr size_t O_KVT   = O_KVC   + SZ(24576ull*1024);          // [512,16,1024]
constexpr size_t O_OC    = O_KVT   + SZ(8192ull*1024);           // [512,48,512]
constexpr size_t O_OT    = O_OC    + SZ(24576ull*512);
constexpr size_t O_CAT   = O_OT    + SZ(24576ull*512);           // [24576,1024]
constexpr size_t O_LOG   = O_CAT   + SZ(24576ull*1024);          // [24576,128]
constexpr size_t O_END   = O_LOG   + SZ(24576ull*128);

__device__ float g_scratch[O_END];

// ---------------------------------------------------------------------------
// group-local barriers: one (cnt, gen) pair per (chain, b-tile) group.
// ---------------------------------------------------------------------------
__device__ unsigned g_gcnt[64 * 32];
__device__ unsigned g_ggen[64 * 32];

__device__ __forceinline__ void group_barrier(int gid, unsigned nblk) {
    __syncthreads();
    __threadfence();
    if (threadIdx.x == 0) {
        volatile unsigned* vg = &g_ggen[gid * 32];
        unsigned my = *vg;
        if (atomicInc(&g_gcnt[gid * 32], nblk - 1u) == nblk - 1u) {
            atomicAdd(&g_ggen[gid * 32], 1u);
        } else {
            while (*vg == my) __nanosleep(32);
        }
    }
    __syncthreads();
}

// ---------------------------------------------------------------------------
__global__ void prep_kernel(const int* __restrict__ li,
                            const float* __restrict__ char_seq,
                            const float* __restrict__ tagset,
                            const float* __restrict__ lang_embeds,
                            float* __restrict__ cs, float* __restrict__ ts) {
    int idx = blockIdx.x * blockDim.x + threadIdx.x;
    const int n1 = 512 * 48 * 192;
    const int n2 = 512 * 16 * 128;
    if (idx < n1) {
        int b = idx / (48 * 192);
        int rem = idx - b * 48 * 192;
        int s = rem / 192, k = rem - s * 192;
        float v;
        if (k < 128) v = char_seq[(b * 48 + s) * 128 + k];
        else         v = lang_embeds[li[li[b]] * 64 + (k - 128)];
        cs[idx] = v;
    } else if (idx < n1 + n2) {
        int j = idx - n1;
        int b = j / (16 * 128);
        int rem = j - b * 16 * 128;
        int s = rem / 128, k = rem - s * 128;
        float v;
        if (k < 64) v = tagset[(b * 16 + s) * 64 + k];
        else        v = lang_embeds[li[li[b]] * 64 + (k - 64)];
        ts[j] = v;
    }
}

__global__ void build_decin(const float* __restrict__ labels, float* __restrict__ decin) {
    int idx = blockIdx.x * blockDim.x + threadIdx.x;
    if (idx >= 512 * 48 * 128) return;
    int t = (idx >> 7) % 48;
    decin[idx] = (t == 0) ? 0.f : labels[idx];
}

// ---------------------------------------------------------------------------
// bf16x3 helpers. x = hi + lo (both bf16): per-product error ~2^-18.
// D += Ah*Bh + Ah*Bl + Al*Bh with fp32 accumulate (m16n8k16).
// ---------------------------------------------------------------------------
__device__ __forceinline__ void split_bf(float x0, float x1,
                                         unsigned& hi2, unsigned& lo2) {
    unsigned h;
    asm("cvt.rn.bf16x2.f32 %0, %1, %2;" : "=r"(h) : "f"(x1), "f"(x0));
    float h0 = __uint_as_float(h << 16);
    float h1 = __uint_as_float(h & 0xffff0000u);
    float l0 = x0 - h0;
    float l1 = x1 - h1;
    unsigned l;
    asm("cvt.rn.bf16x2.f32 %0, %1, %2;" : "=r"(l) : "f"(l1), "f"(l0));
    hi2 = h; lo2 = l;
}

__device__ __forceinline__ void mma16bf(float* c, const unsigned* a, const unsigned* b) {
    asm volatile(
        "mma.sync.aligned.m16n8k16.row.col.f32.bf16.bf16.f32 "
        "{%0,%1,%2,%3}, {%4,%5,%6,%7}, {%8,%9}, {%0,%1,%2,%3};\n"
        : "+f"(c[0]), "+f"(c[1]), "+f"(c[2]), "+f"(c[3])
        : "r"(a[0]), "r"(a[1]), "r"(a[2]), "r"(a[3]), "r"(b[0]), "r"(b[1]));
}

// k2 permutation within each 8-word group so the fragment pair (k2, k2+4)
// is one LDS.64: pos = group*8 + (k2&3)*2 + ((k2>>2)&1)
__device__ __forceinline__ int permk2(int k2) {
    return (k2 >> 3) * 8 + (k2 & 3) * 2 + ((k2 >> 2) & 1);
}

// ---------------------------------------------------------------------------
// GEMM: C[m,n] = sum_k A[m,k]*W[n,k] + bias[n]. 128x128 tile, K-STEP 64,
// 512 threads = 16 warps (4m x 4n), warp tile 32x32, double-buffered.
// smem per stage (uint32 words): Ah[128*40] Al Bh Bl (rows: 32 data words in
// 4 perm-groups of 8, stride 40 => conflict-free half-warp LDS.64 phases).
// Stage = 20480 words; double buffer = 163840 bytes.
// One __syncthreads per 64-k tile.
// ---------------------------------------------------------------------------
__device__ __forceinline__ void g_ldg(const float* __restrict__ A,
                                      const float* __restrict__ W,
                                      int K, int bm, int bn, int k0, int tid,
                                      float4* av, float4* wv) {
#pragma unroll
    for (int i = 0; i < 4; i++) {
        int idx = tid + i * 512;
        int row = idx >> 4, fc = idx & 15;
        av[i] = *(const float4*)(A + (size_t)(bm + row) * K + k0 + fc * 4);
        wv[i] = *(const float4*)(W + (size_t)(bn + row) * K + k0 + fc * 4);
    }
}

__device__ __forceinline__ void g_sts(unsigned* __restrict__ buf, int tid,
                                      const float4* av, const float4* wv) {
    unsigned* Ah = buf;
    unsigned* Al = buf + 5120;
    unsigned* Bh = buf + 10240;
    unsigned* Bl = buf + 15360;
#pragma unroll
    for (int i = 0; i < 4; i++) {
        int idx = tid + i * 512;
        int row = idx >> 4, fc = idx & 15;
        int pa = row * 40 + permk2(fc * 2);
        int pb = row * 40 + permk2(fc * 2 + 1);
        unsigned h, l;
        split_bf(av[i].x, av[i].y, h, l); Ah[pa] = h; Al[pa] = l;
        split_bf(av[i].z, av[i].w, h, l); Ah[pb] = h; Al[pb] = l;
        split_bf(wv[i].x, wv[i].y, h, l); Bh[pa] = h; Bl[pa] = l;
        split_bf(wv[i].z, wv[i].w, h, l); Bh[pb] = h; Bl[pb] = l;
    }
}

__device__ __forceinline__ void g_compute(const unsigned* __restrict__ buf,
                                          int wm, int wn, int gid, int tig,
                                          float (&acc)[2][4][4]) {
    const unsigned* Ah = buf;
    const unsigned* Al = buf + 5120;
    const unsigned* Bh = buf + 10240;
    const unsigned* Bl = buf + 15360;
#pragma unroll
    for (int s = 0; s < 4; s++) {
        unsigned ah[2][4], al[2][4];
#pragma unroll
        for (int mt = 0; mt < 2; mt++) {
            int o = (wm * 32 + mt * 16 + gid) * 40 + s * 8 + tig * 2;
            uint2 p = *(const uint2*)(Ah + o);
            uint2 q = *(const uint2*)(Ah + o + 320);   // +8 rows
            ah[mt][0] = p.x; ah[mt][2] = p.y; ah[mt][1] = q.x; ah[mt][3] = q.y;
            uint2 r = *(const uint2*)(Al + o);
            uint2 t = *(const uint2*)(Al + o + 320);
            al[mt][0] = r.x; al[mt][2] = r.y; al[mt][1] = t.x; al[mt][3] = t.y;
        }
        unsigned bh[4][2], bl[4][2];
#pragma unroll
        for (int j = 0; j < 4; j++) {
            int o = (wn * 32 + j * 8 + gid) * 40 + s * 8 + tig * 2;
            uint2 p = *(const uint2*)(Bh + o);
            bh[j][0] = p.x; bh[j][1] = p.y;
            uint2 q = *(const uint2*)(Bl + o);
            bl[j][0] = q.x; bl[j][1] = q.y;
        }
#pragma unroll
        for (int mt = 0; mt < 2; mt++)
#pragma unroll
            for (int j = 0; j < 4; j++) {
                float* c = acc[mt][j];
                mma16bf(c, ah[mt], bh[j]);
                mma16bf(c, ah[mt], bl[j]);
                mma16bf(c, al[mt], bh[j]);
            }
    }
}

__global__ __launch_bounds__(512) void gemm_mma(
    const float* __restrict__ A, const float* __restrict__ W,
    const float* __restrict__ bias, float* __restrict__ C,
    int M, int N, int K, int ldc)
{
    extern __shared__ unsigned gsb[];
    unsigned* bufs[2] = { gsb, gsb + 20480 };
    const int bm = blockIdx.y * 128;
    const int bn = blockIdx.x * 128;
    const int tid = threadIdx.x;
    const int wid = tid >> 5, lane = tid & 31;
    const int wm = wid >> 2, wn = wid & 3;
    const int gid = lane >> 2, tig = lane & 3;

    float acc[2][4][4];
#pragma unroll
    for (int i = 0; i < 2; i++)
#pragma unroll
        for (int j = 0; j < 4; j++)
#pragma unroll
            for (int r = 0; r < 4; r++) acc[i][j][r] = 0.f;

    const int NT = K >> 6;                // >= 2 at all call sites
    float4 av[4], wv[4];

    g_ldg(A, W, K, bm, bn, 0, tid, av, wv);
    g_sts(bufs[0], tid, av, wv);
    __syncthreads();
    g_ldg(A, W, K, bm, bn, 64, tid, av, wv);

    for (int kt = 0; kt < NT; kt++) {
        if (kt + 1 < NT) g_sts(bufs[(kt + 1) & 1], tid, av, wv);
        if (kt + 2 < NT) g_ldg(A, W, K, bm, bn, (kt + 2) * 64, tid, av, wv);
        g_compute(bufs[kt & 1], wm, wn, gid, tig, acc);
        __syncthreads();
    }

#pragma unroll
    for (int mt = 0; mt < 2; mt++)
#pragma unroll
        for (int nt = 0; nt < 4; nt++) {
            int row = bm + wm * 32 + mt * 16 + gid;
            int col = bn + wn * 32 + nt * 8 + tig * 2;
            float b0 = bias[col], b1 = bias[col + 1];
            float* c = acc[mt][nt];
            float* p0 = C + (size_t)row * ldc + col;
            float* p1 = C + (size_t)(row + 8) * ldc + col;
            p0[0] = c[0] + b0; p0[1] = c[1] + b1;
            p1[0] = c[2] + b0; p1[1] = c[3] + b1;
        }
}

// ---------------------------------------------------------------------------
// Persistent tensor-core LSTM (bf16x3), K-STEP 64, group-local barriers.
// 128 blocks x 512 threads, 1 block/SM.
// Block tile: BM batch x 64 j x 4 gates (N=256), 16 warps, each warp N=16.
// smem per stage (words): Ah[BM*40] Al[BM*40] Bh[256*40] Bl[256*40] = 23040;
// double buffer = 184320 bytes. Epilogue reuses smem as float EB[BM][260].
// ---------------------------------------------------------------------------
struct PChain {
    const float* xg0;  long dxg;      // Xg(t) = xg0 + t*dxg
    float*       ho0;  long dho;      // ho(t) = ho0 + t*dho; hp(t)=ho(t-1)
    const float* hp_init;             // t==0 h (nullptr => zeros)
    const float* cp_init;             // t==0 c (nullptr => zeros)
    const float* whh;                 // [4H,H]
    float*       cbuf;                // 2 x [512,H] ping-pong
    int ldx, ldh, ldo, ldh_init;
};
struct PArgs { PChain c[2]; };

__device__ __forceinline__ float sigm(float x) { return 1.f / (1.f + expf(-x)); }

template<int BM>
__device__ __forceinline__ void l_ldg(const float* hp, int ldh, const float* whh,
                                      int H, int b0, int j0, int k0, int tid,
                                      float4* av, float4* wv) {
    {   // h tile: BM x 64 floats = BM*16 float4; BM=32 -> exactly 512 threads
        int r = tid >> 4, fc = tid & 15;
        av[0] = *(const float4*)(hp + (size_t)(b0 + r) * ldh + k0 + fc * 4);
    }
#pragma unroll
    for (int i = 0; i < 8; i++) {
        int idx = tid + i * 512;
        int r = idx >> 4, fc = idx & 15;
        int g = r >> 6, jl = r & 63;
        wv[i] = *(const float4*)(whh + (size_t)(g * H + j0 + jl) * H + k0 + fc * 4);
    }
}

template<int BM>
__device__ __forceinline__ void l_sts(unsigned* __restrict__ buf, int tid,
                                      const float4* av, const float4* wv) {
    unsigned* Ah = buf;
    unsigned* Al = buf + BM * 40;
    unsigned* Bh = buf + 2 * BM * 40;
    unsigned* Bl = buf + 2 * BM * 40 + 10240;
    {
        int r = tid >> 4, fc = tid & 15;
        int pa = r * 40 + permk2(fc * 2);
        int pb = r * 40 + permk2(fc * 2 + 1);
        unsigned h, l;
        split_bf(av[0].x, av[0].y, h, l); Ah[pa] = h; Al[pa] = l;
        split_bf(av[0].z, av[0].w, h, l); Ah[pb] = h; Al[pb] = l;
    }
#pragma unroll
    for (int i = 0; i < 8; i++) {
        int idx = tid + i * 512;
        int r = idx >> 4, fc = idx & 15;
        int pa = r * 40 + permk2(fc * 2);
        int pb = r * 40 + permk2(fc * 2 + 1);
        unsigned h, l;
        split_bf(wv[i].x, wv[i].y, h, l); Bh[pa] = h; Bl[pa] = l;
        split_bf(wv[i].z, wv[i].w, h, l); Bh[pb] = h; Bl[pb] = l;
    }
}

template<int BM>
__device__ __forceinline__ void l_compute(const unsigned* __restrict__ buf,
                                          int wn, int gid, int tig,
                                          float (&acc)[BM/16][2][4]) {
    constexpr int MT = BM / 16;
    const unsigned* Ah = buf;
    const unsigned* Al = buf + BM * 40;
    const unsigned* Bh = buf + 2 * BM * 40;
    const unsigned* Bl = buf + 2 * BM * 40 + 10240;
#pragma unroll
    for (int s = 0; s < 4; s++) {
        unsigned ah[MT][4], al[MT][4];
#pragma unroll
        for (int mt = 0; mt < MT; mt++) {
            int o = (mt * 16 + gid) * 40 + s * 8 + tig * 2;
            uint2 p = *(const uint2*)(Ah + o);
            uint2 q = *(const uint2*)(Ah + o + 320);
            ah[mt][0] = p.x; ah[mt][2] = p.y; ah[mt][1] = q.x; ah[mt][3] = q.y;
            uint2 r = *(const uint2*)(Al + o);
            uint2 t = *(const uint2*)(Al + o + 320);
            al[mt][0] = r.x; al[mt][2] = r.y; al[mt][1] = t.x; al[mt][3] = t.y;
        }
        unsigned bh[2][2], bl[2][2];
#pragma unroll
        for (int nj = 0; nj < 2; nj++) {
            int o = (wn * 16 + nj * 8 + gid) * 40 + s * 8 + tig * 2;
            uint2 p = *(const uint2*)(Bh + o);
            bh[nj][0] = p.x; bh[nj][1] = p.y;
            uint2 q = *(const uint2*)(Bl + o);
            bl[nj][0] = q.x; bl[nj][1] = q.y;
        }
#pragma unroll
        for (int mt = 0; mt < MT; mt++)
#pragma unroll
            for (int nj = 0; nj < 2; nj++) {
                float* c = acc[mt][nj];
                mma16bf(c, ah[mt], bh[nj]);
                mma16bf(c, ah[mt], bl[nj]);
                mma16bf(c, al[mt], bh[nj]);
            }
    }
}

template<int BM>
__device__ void lstm_body(const float* Xg, const float* hp, const float* cp,
                          const float* whh, float* ho, float* co,
                          int ldx, int ldh, int ldo, int H,
                          unsigned* sb, int j0, int b0, int tid) {
    constexpr int MT = BM / 16;
    constexpr int BUFSZ = (2 * BM + 512) * 40;   // 23040 for BM=32
    unsigned* bufs[2] = { sb, sb + BUFSZ };
    const int lane = tid & 31;
    const int wn = tid >> 5;
    const int gid = lane >> 2, tig = lane & 3;

    if (hp) {
        float acc[MT][2][4];
#pragma unroll
        for (int mt = 0; mt < MT; mt++)
#pragma unroll
            for (int nj = 0; nj < 2; nj++)
#pragma unroll
                for (int r = 0; r < 4; r++) acc[mt][nj][r] = 0.f;

        const int NKT = H >> 6;              // 4 (H=256) or 8 (H=512)
        float4 av[1], wv[8];

        l_ldg<BM>(hp, ldh, whh, H, b0, j0, 0, tid, av, wv);
        l_sts<BM>(bufs[0], tid, av, wv);
        __syncthreads();
        l_ldg<BM>(hp, ldh, whh, H, b0, j0, 64, tid, av, wv);

        for (int kt = 0; kt < NKT; kt++) {
            if (kt + 1 < NKT) l_sts<BM>(bufs[(kt + 1) & 1], tid, av, wv);
            if (kt + 2 < NKT) l_ldg<BM>(hp, ldh, whh, H, b0, j0, (kt + 2) * 64, tid, av, wv);
            l_compute<BM>(bufs[kt & 1], wn, gid, tig, acc);
            __syncthreads();
        }

        // gate exchange: EB[b_local][flat_col], stride 260 (floats)
        float* EB = (float*)sb;
#pragma unroll
        for (int mt = 0; mt < MT; mt++)
#pragma unroll
            for (int nj = 0; nj < 2; nj++) {
                int col = wn * 16 + nj * 8 + tig * 2;
                float* c = acc[mt][nj];
                EB[(mt * 16 + gid) * 260 + col]         = c[0];
                EB[(mt * 16 + gid) * 260 + col + 1]     = c[1];
                EB[(mt * 16 + gid + 8) * 260 + col]     = c[2];
                EB[(mt * 16 + gid + 8) * 260 + col + 1] = c[3];
            }
        __syncthreads();
    }

    const float* EB = (const float*)sb;
    const int jl = tid & 63;
    const int brow = tid >> 6;
#pragma unroll
    for (int i = 0; i < BM / 8; i++) {
        int bl_ = brow + i * 8;
        int b = b0 + bl_;
        const float* xr = Xg + (size_t)b * ldx;
        int j = j0 + jl;
        float a0 = 0.f, a1 = 0.f, a2 = 0.f, a3 = 0.f;
        if (hp) {
            a0 = EB[bl_ * 260 + jl];
            a1 = EB[bl_ * 260 + 64 + jl];
            a2 = EB[bl_ * 260 + 128 + jl];
            a3 = EB[bl_ * 260 + 192 + jl];
        }
        float gi = a0 + xr[j];
        float gf = a1 + xr[H + j];
        float gg = a2 + xr[2 * H + j];
        float go = a3 + xr[3 * H + j];
        float cpv = cp ? cp[(size_t)b * H + j] : 0.f;
        float cc = sigm(gf) * cpv + sigm(gi) * tanhf(gg);
        co[(size_t)b * H + j] = cc;
        ho[(size_t)b * ldo + j] = sigm(go) * tanhf(cc);
    }
}

template<int BM>
__global__ __launch_bounds__(512) void lstm_persist(PArgs pa, int H, int nsteps) {
    extern __shared__ unsigned lsb[];
    const PChain ch = pa.c[blockIdx.z];
    const int j0 = blockIdx.x * 64;
    const int b0 = blockIdx.y * BM;
    const int tid = threadIdx.x;
    const size_t CB = 512 * (size_t)H;
    const int grp = blockIdx.z * gridDim.y + blockIdx.y;
    const unsigned nblk = gridDim.x;

    for (int t = 0; t < nsteps; t++) {
        const float* Xg = ch.xg0 + (long)t * ch.dxg;
        const float* hp;
        const float* cp;
        int ldh;
        if (t == 0) { hp = ch.hp_init; cp = ch.cp_init; ldh = ch.ldh_init; }
        else {
            hp = ch.ho0 + (long)(t - 1) * ch.dho;
            cp = ch.cbuf + (size_t)(t & 1) * CB;
            ldh = ch.ldh;
        }
        float* ho = ch.ho0 + (long)t * ch.dho;
        float* co = ch.cbuf + (size_t)((t + 1) & 1) * CB;

        lstm_body<BM>(Xg, hp, cp, ch.whh, ho, co,
                      ch.ldx, ldh, ch.ldo, H, lsb, j0, b0, tid);
        if (t + 1 < nsteps) group_barrier(grp, nblk);
    }
}

__global__ void build_h0c0(const float* __restrict__ CO, const float* __restrict__ TO,
                           const float* __restrict__ ccf, const float* __restrict__ ctf,
                           float* __restrict__ h0, float* __restrict__ c0) {
    int idx = blockIdx.x * blockDim.x + threadIdx.x;
    if (idx >= 512 * 512) return;
    int b = idx >> 9, j = idx & 511;
    float hv, cv;
    if (j < 256) { hv = CO[((size_t)b * 48 + 47) * 512 + j];        cv = ccf[b * 256 + j]; }
    else         { hv = TO[((size_t)b * 16 + 15) * 512 + (j - 256)]; cv = ctf[b * 256 + (j - 256)]; }
    h0[idx] = hv;
    c0[idx] = cv;
}

// ---------------------------------------------------------------------------
// Single-head attention, one block per batch element.
// ---------------------------------------------------------------------------
__global__ __launch_bounds__(256) void attn_kernel(
    const float* __restrict__ Q, const float* __restrict__ KV,
    float* __restrict__ O, int Lk)
{
    const int b = blockIdx.x;
    const int tid = threadIdx.x;
    __shared__ float Qs[48][68];
    __shared__ float Ks[48][68];
    __shared__ float s[48][48];

    const float* Qb = Q + (size_t)b * 48 * 512;
    const float* Kb = KV + (size_t)b * Lk * 1024;

    float acc[9];
#pragma unroll
    for (int i = 0; i < 9; i++) acc[i] = 0.f;

    for (int e0 = 0; e0 < 512; e0 += 64) {
        __syncthreads();
        for (int idx = tid; idx < 48 * 16; idx += 256) {
            int r = idx >> 4, cc = (idx & 15) << 2;
            *(float4*)&Qs[r][cc] = *(const float4*)(Qb + (size_t)r * 512 + e0 + cc);
        }
        for (int idx = tid; idx < Lk * 16; idx += 256) {
            int r = idx >> 4, cc = (idx & 15) << 2;
            *(float4*)&Ks[r][cc] = *(const float4*)(Kb + (size_t)r * 1024 + e0 + cc);
        }
        __syncthreads();
        int pi = 0;
        for (int idx = tid; idx < 48 * Lk; idx += 256, pi++) {
            int q = idx / Lk, k = idx - q * Lk;
            float sum = 0.f;
#pragma unroll 16
            for (int e = 0; e < 64; e++) sum += Qs[q][e] * Ks[k][e];
            acc[pi] += sum;
        }
    }
    __syncthreads();
    {
        const float scale = 0.04419417382415922f;   // 1/sqrt(512)
        int pi = 0;
        for (int idx = tid; idx < 48 * Lk; idx += 256, pi++) {
            int q = idx / Lk, k = idx - q * Lk;
            s[q][k] = acc[pi] * scale;
        }
    }
    __syncthreads();
    if (tid < 48) {
        float m = -1e30f;
        for (int k = 0; k < Lk; k++) m = fmaxf(m, s[tid][k]);
        float sum = 0.f;
        for (int k = 0; k < Lk; k++) { float e = expf(s[tid][k] - m); s[tid][k] = e; sum += e; }
        float inv = 1.f / sum;
        for (int k = 0; k < Lk; k++) s[tid][k] *= inv;
    }
    __syncthreads();

    float* Ob = O + (size_t)b * 48 * 512;
    const float* Vb = KV + (size_t)b * Lk * 1024 + 512;
    for (int e0 = 0; e0 < 512; e0 += 64) {
        for (int idx = tid; idx < Lk * 16; idx += 256) {
            int r = idx >> 4, cc = (idx & 15) << 2;
            *(float4*)&Ks[r][cc] = *(const float4*)(Vb + (size_t)r * 1024 + e0 + cc);
        }
        __syncthreads();
        for (int idx = tid; idx < 48 * 64; idx += 256) {
            int q = idx >> 6, e = idx & 63;
            float sum = 0.f;
            for (int k = 0; k < Lk; k++) sum += s[q][k] * Ks[k][e];
            Ob[(size_t)q * 512 + e0 + e] = sum;
        }
        __syncthreads();
    }
}

// ---------------------------------------------------------------------------
// Exact 1.5-entmax via warp bisection; one warp per row of 128.
// ---------------------------------------------------------------------------
__global__ __launch_bounds__(256) void entmax_kernel(
    const float* __restrict__ logits, float* __restrict__ out, int nrows)
{
    int row = blockIdx.x * 8 + (threadIdx.x >> 5);
    if (row >= nrows) return;
    int lane = threadIdx.x & 31;
    const float* x = logits + (size_t)row * 128;
    float z[4];
    float m = -1e30f;
#pragma unroll
    for (int i = 0; i < 4; i++) { z[i] = x[lane + 32 * i] * 0.5f; m = fmaxf(m, z[i]); }
#pragma unroll
    for (int o = 16; o; o >>= 1) m = fmaxf(m, __shfl_xor_sync(0xffffffffu, m, o));
#pragma unroll
    for (int i = 0; i < 4; i++) z[i] -= m;
    float lo = -1.f, hi = 0.f;
    for (int it = 0; it < 35; it++) {
        float tau = 0.5f * (lo + hi);
        float f = 0.f;
#pragma unroll
        for (int i = 0; i < 4; i++) { float d = fmaxf(z[i] - tau, 0.f); f += d * d; }
#pragma unroll
        for (int o = 16; o; o >>= 1) f += __shfl_xor_sync(0xffffffffu, f, o);
        if (f >= 1.f) lo = tau; else hi = tau;
    }
    float tau = 0.5f * (lo + hi);
    float* yo = out + (size_t)row * 128;
#pragma unroll
    for (int i = 0; i < 4; i++) { float d = fmaxf(z[i] - tau, 0.f); yo[lane + 32 * i] = d * d; }
}

// ---------------------------------------------------------------------------
extern "C" void kernel_launch(void* const* d_in, const int* in_sizes, int n_in,
                              void* d_out, int out_size) {
    const int*   li          = (const int*)  d_in[0];
    const float* char_seq    = (const float*)d_in[1];
    const float* tagset      = (const float*)d_in[2];
    const float* labels      = (const float*)d_in[3];
    const float* lang_embeds = (const float*)d_in[4];
    const float* c_w_ih_f    = (const float*)d_in[5];
    const float* c_w_hh_f    = (const float*)d_in[6];
    const float* c_b_f       = (const float*)d_in[7];
    const float* c_w_ih_b    = (const float*)d_in[8];
    const float* c_w_hh_b    = (const float*)d_in[9];
    const float* c_b_b       = (const float*)d_in[10];
    const float* t_w_ih_f    = (const float*)d_in[11];
    const float* t_w_hh_f    = (const float*)d_in[12];
    const float* t_b_f       = (const float*)d_in[13];
    const float* t_w_ih_b    = (const float*)d_in[14];
    const float* t_w_hh_b    = (const float*)d_in[15];
    const float* t_b_b       = (const float*)d_in[16];
    const float* cell_w_ih   = (const float*)d_in[17];
    const float* cell_w_hh   = (const float*)d_in[18];
    const float* cell_b      = (const float*)d_in[19];
    const float* ch_in_w     = (const float*)d_in[20];
    const float* ch_in_b     = (const float*)d_in[21];
    const float* ch_out_w    = (const float*)d_in[22];
    const float* ch_out_b    = (const float*)d_in[23];
    const float* tg_in_w     = (const float*)d_in[24];
    const float* tg_in_b     = (const float*)d_in[25];
    const float* tg_out_w    = (const float*)d_in[26];
    const float* tg_out_b    = (const float*)d_in[27];
    const float* fc_w        = (const float*)d_in[28];
    const float* fc_b        = (const float*)d_in[29];
    float* OUT = (float*)d_out;

    float* S = nullptr;
    cudaGetSymbolAddress((void**)&S, g_scratch);

    const int GSM = 163840;   // gemm_mma: 2 x 20480 words
    const int LSM = 184320;   // lstm_persist<32>: 2 x 23040 words
    static bool attr_set = false;
    if (!attr_set) {
        cudaFuncSetAttribute(gemm_mma, cudaFuncAttributeMaxDynamicSharedMemorySize, GSM);
        cudaFuncSetAttribute(lstm_persist<32>, cudaFuncAttributeMaxDynamicSharedMemorySize, LSM);
        attr_set = true;
    }

    // 1) input prep
    prep_kernel<<<CDIV(5767168, 256), 256>>>(li, char_seq, tagset, lang_embeds,
                                             S + O_CS, S + O_TS);
    build_decin<<<CDIV(3145728, 256), 256>>>(labels, S + O_DECIN);

    // 2) input-projection GEMMs
    gemm_mma<<<dim3(8, 192), 512, GSM>>>(S + O_CS, c_w_ih_f, c_b_f, S + O_XCF, 24576, 1024, 192, 1024);
    gemm_mma<<<dim3(8, 192), 512, GSM>>>(S + O_CS, c_w_ih_b, c_b_b, S + O_XCB, 24576, 1024, 192, 1024);
    gemm_mma<<<dim3(8,  64), 512, GSM>>>(S + O_TS, t_w_ih_f, t_b_f, S + O_XTF,  8192, 1024, 128, 1024);
    gemm_mma<<<dim3(8,  64), 512, GSM>>>(S + O_TS, t_w_ih_b, t_b_b, S + O_XTB,  8192, 1024, 128, 1024);
    gemm_mma<<<dim3(16,192), 512, GSM>>>(S + O_DECIN, cell_w_ih, cell_b, S + O_XDEC, 24576, 2048, 128, 2048);

    // 3) encoder recurrences — persistent kernels, group-local barriers
    {
        PArgs A;  // char: fwd + bwd, 48 steps, H=256, grid (4,16,2)=128 blocks
        A.c[0] = { S + O_XCF, 1024,
                   S + O_CO, 512,
                   nullptr, nullptr, c_w_hh_f, S + O_CCF,
                   48 * 1024, 48 * 512, 48 * 512, 0 };
        A.c[1] = { S + O_XCB + 47ll * 1024, -1024,
                   S + O_CO + 47ll * 512 + 256, -512,
                   nullptr, nullptr, c_w_hh_b, S + O_CCB,
                   48 * 1024, 48 * 512, 48 * 512, 0 };
        lstm_persist<32><<<dim3(4, 16, 2), 512, LSM>>>(A, 256, 48);

        PArgs T;  // tag: fwd + bwd, 16 steps, H=256
        T.c[0] = { S + O_XTF, 1024,
                   S + O_TO, 512,
                   nullptr, nullptr, t_w_hh_f, S + O_CTF,
                   16 * 1024, 16 * 512, 16 * 512, 0 };
        T.c[1] = { S + O_XTB + 15ll * 1024, -1024,
                   S + O_TO + 15ll * 512 + 256, -512,
                   nullptr, nullptr, t_w_hh_b, S + O_CTB,
                   16 * 1024, 16 * 512, 16 * 512, 0 };
        lstm_persist<32><<<dim3(4, 16, 2), 512, LSM>>>(T, 256, 16);
    }

    // 4) initial decoder state
    build_h0c0<<<1024, 256>>>(S + O_CO, S + O_TO, S + O_CCF, S + O_CTF,
                              S + O_H0, S + O_C0);

    // 5) decoder recurrence — persistent kernel, grid (8,16,1)=128 blocks
    {
        PArgs D;
        D.c[0] = { S + O_XDEC, 2048,
                   S + O_HS, 512,
                   S + O_H0, S + O_C0, cell_w_hh, S + O_DC,
                   48 * 2048, 48 * 512, 48 * 512, 512 };
        D.c[1] = D.c[0];
        lstm_persist<32><<<dim3(8, 16, 1), 512, LSM>>>(D, 512, 48);
    }

    // 6) attention projections
    gemm_mma<<<dim3(4, 192), 512, GSM>>>(S + O_HS, ch_in_w, ch_in_b, S + O_QC, 24576, 512, 512, 512);
    gemm_mma<<<dim3(4, 192), 512, GSM>>>(S + O_HS, tg_in_w, tg_in_b, S + O_QT, 24576, 512, 512, 512);
    gemm_mma<<<dim3(8, 192), 512, GSM>>>(S + O_CO, ch_in_w + 512 * 512, ch_in_b + 512,
                                         S + O_KVC, 24576, 1024, 512, 1024);
    gemm_mma<<<dim3(8,  64), 512, GSM>>>(S + O_TO, tg_in_w + 512 * 512, tg_in_b + 512,
                                         S + O_KVT,  8192, 1024, 512, 1024);

    // 7) attention cores
    attn_kernel<<<512, 256>>>(S + O_QC, S + O_KVC, S + O_OC, 48);
    attn_kernel<<<512, 256>>>(S + O_QT, S + O_KVT, S + O_OT, 16);

    // 8) output projections straight into the concat buffer
    gemm_mma<<<dim3(4, 192), 512, GSM>>>(S + O_OC, ch_out_w, ch_out_b, S + O_CAT,       24576, 512, 512, 1024);
    gemm_mma<<<dim3(4, 192), 512, GSM>>>(S + O_OT, tg_out_w, tg_out_b, S + O_CAT + 512, 24576, 512, 512, 1024);

    // 9) final FC + entmax15
    gemm_mma<<<dim3(1, 192), 512, GSM>>>(S + O_CAT, fc_w, fc_b, S + O_LOG, 24576, 128, 1024, 128);
    entmax_kernel<<<3072, 256>>>(S + O_LOG, OUT, 24576);
}

// round 16
// speedup vs baseline: 1.1072x; 1.0536x over previous
#include <cuda_runtime.h>
#include <cuda_bf16.h>
#include <math.h>

#define CDIV(a,b) (((a)+(b)-1)/(b))

// Dimensions: B=512, SC=48, ST=16, E=512, H=256, N_CHARS=128, N_TAGS=64
constexpr size_t SZ(size_t n) { return (n + 255) & ~(size_t)255; }

// Packed format: for a row of K fp32 values, word[2p] = bf16x2(hi of v[2p],v[2p+1]),
// word[2p+1] = bf16x2(lo). Same byte count as fp32.
constexpr size_t O_CS    = 0;                                    // packed [24576][192]
constexpr size_t O_TS    = O_CS    + SZ(24576ull*192);           // packed [8192][128]
constexpr size_t O_DECIN = O_TS    + SZ(8192ull*128);            // packed [24576][128]
constexpr size_t O_XCF   = O_DECIN + SZ(24576ull*128);           // fp32 [24576][1024]
constexpr size_t O_XCB   = O_XCF   + SZ(24576ull*1024);
constexpr size_t O_XTF   = O_XCB   + SZ(24576ull*1024);          // fp32 [8192][1024]
constexpr size_t O_XTB   = O_XTF   + SZ(8192ull*1024);
constexpr size_t O_XDEC  = O_XTB   + SZ(8192ull*1024);           // fp32 [24576][2048]
constexpr size_t O_CO    = O_XDEC  + SZ(24576ull*2048);          // packed [24576][512]
constexpr size_t O_TO    = O_CO    + SZ(24576ull*512);           // packed [8192][512]
constexpr size_t O_HS    = O_TO    + SZ(8192ull*512);            // packed [24576][512]
constexpr size_t O_CCF   = O_HS    + SZ(24576ull*512);           // fp32 2x[512,256]
constexpr size_t O_CCB   = O_CCF   + SZ(2ull*512*256);
constexpr size_t O_CTF   = O_CCB   + SZ(2ull*512*256);
constexpr size_t O_CTB   = O_CTF   + SZ(2ull*512*256);
constexpr size_t O_DC    = O_CTB   + SZ(2ull*512*256);           // fp32 2x[512,512]
constexpr size_t O_H0    = O_DC    + SZ(2ull*512*512);           // packed [512][512]
constexpr size_t O_C0    = O_H0    + SZ(512ull*512);             // fp32 [512][512]
constexpr size_t O_QC    = O_C0    + SZ(512ull*512);             // fp32 [24576][512]
constexpr size_t O_QT    = O_QC    + SZ(24576ull*512);
constexpr size_t O_KVC   = O_QT    + SZ(24576ull*512);           // fp32 [24576][1024]
constexpr size_t O_KVT   = O_KVC   + SZ(24576ull*1024);          // fp32 [8192][1024]
constexpr size_t O_OC    = O_KVT   + SZ(8192ull*1024);           // packed [24576][512]
constexpr size_t O_OT    = O_OC    + SZ(24576ull*512);
constexpr size_t O_CAT   = O_OT    + SZ(24576ull*512);           // packed [24576][1024]
constexpr size_t O_LOG   = O_CAT   + SZ(24576ull*1024);          // fp32 [24576][128]
// packed weights
constexpr size_t O_PCIF  = O_LOG   + SZ(24576ull*128);           // [1024][192]
constexpr size_t O_PCIB  = O_PCIF  + SZ(196608);
constexpr size_t O_PTIF  = O_PCIB  + SZ(196608);                 // [1024][128]
constexpr size_t O_PTIB  = O_PTIF  + SZ(131072);
constexpr size_t O_PDI   = O_PTIB  + SZ(131072);                 // [2048][128]
constexpr size_t O_PCHI  = O_PDI   + SZ(262144);                 // [1536][512]
constexpr size_t O_PTGI  = O_PCHI  + SZ(786432);
constexpr size_t O_PCHO  = O_PTGI  + SZ(786432);                 // [512][512]
constexpr size_t O_PTGO  = O_PCHO  + SZ(262144);
constexpr size_t O_PFC   = O_PTGO  + SZ(262144);                 // [128][1024]
constexpr size_t O_PCHF  = O_PFC   + SZ(131072);                 // [1024][256]
constexpr size_t O_PCHB  = O_PCHF  + SZ(262144);
constexpr size_t O_PTHF  = O_PCHB  + SZ(262144);
constexpr size_t O_PTHB  = O_PTHF  + SZ(262144);
constexpr size_t O_PDHH  = O_PTHB  + SZ(262144);                 // [2048][512]
constexpr size_t O_END   = O_PDHH  + SZ(1048576);

__device__ float g_scratch[O_END];

// ---------------------------------------------------------------------------
// group-local barriers
// ---------------------------------------------------------------------------
__device__ unsigned g_gcnt[64 * 32];
__device__ unsigned g_ggen[64 * 32];

__device__ __forceinline__ void group_barrier(int gid, unsigned nblk) {
    __syncthreads();
    __threadfence();
    if (threadIdx.x == 0) {
        volatile unsigned* vg = &g_ggen[gid * 32];
        unsigned my = *vg;
        if (atomicInc(&g_gcnt[gid * 32], nblk - 1u) == nblk - 1u) {
            atomicAdd(&g_ggen[gid * 32], 1u);
        } else {
            while (*vg == my) __nanosleep(32);
        }
    }
    __syncthreads();
}

// ---------------------------------------------------------------------------
// bf16x3 helpers
// ---------------------------------------------------------------------------
__device__ __forceinline__ void split_bf(float x0, float x1,
                                         unsigned& hi2, unsigned& lo2) {
    unsigned h;
    asm("cvt.rn.bf16x2.f32 %0, %1, %2;" : "=r"(h) : "f"(x1), "f"(x0));
    float h0 = __uint_as_float(h << 16);
    float h1 = __uint_as_float(h & 0xffff0000u);
    float l0 = x0 - h0;
    float l1 = x1 - h1;
    unsigned l;
    asm("cvt.rn.bf16x2.f32 %0, %1, %2;" : "=r"(l) : "f"(l1), "f"(l0));
    hi2 = h; lo2 = l;
}

__device__ __forceinline__ void mma16bf(float* c, const unsigned* a, const unsigned* b) {
    asm volatile(
        "mma.sync.aligned.m16n8k16.row.col.f32.bf16.bf16.f32 "
        "{%0,%1,%2,%3}, {%4,%5,%6,%7}, {%8,%9}, {%0,%1,%2,%3};\n"
        : "+f"(c[0]), "+f"(c[1]), "+f"(c[2]), "+f"(c[3])
        : "r"(a[0]), "r"(a[1]), "r"(a[2]), "r"(a[3]), "r"(b[0]), "r"(b[1]));
}

__device__ __forceinline__ int permk2(int k2) {
    return (k2 >> 3) * 8 + (k2 & 3) * 2 + ((k2 >> 2) & 1);
}

// pre-split any fp32 matrix into the packed interleaved hi/lo word format
__global__ void wsplit_pack(const float* __restrict__ w,
                            unsigned* __restrict__ out, int npairs) {
    int idx = blockIdx.x * blockDim.x + threadIdx.x;
    if (idx >= npairs) return;
    unsigned h, l;
    split_bf(w[2 * idx], w[2 * idx + 1], h, l);
    out[2 * idx] = h;
    out[2 * idx + 1] = l;
}

// ---------------------------------------------------------------------------
// prep: emit packed cs / ts
// ---------------------------------------------------------------------------
__global__ void prep_kernel(const int* __restrict__ li,
                            const float* __restrict__ char_seq,
                            const float* __restrict__ tagset,
                            const float* __restrict__ lang_embeds,
                            unsigned* __restrict__ cs, unsigned* __restrict__ ts) {
    int idx = blockIdx.x * blockDim.x + threadIdx.x;
    const int n1 = 512 * 48 * 96;     // cs pairs
    const int n2 = 512 * 16 * 64;     // ts pairs
    if (idx < n1) {
        int b = idx / (48 * 96);
        int rem = idx - b * 48 * 96;
        int s = rem / 96, p = rem - s * 96;
        float v0, v1;
        if (p < 64) {
            const float* src = char_seq + ((size_t)(b * 48 + s)) * 128 + 2 * p;
            v0 = src[0]; v1 = src[1];
        } else {
            const float* e = lang_embeds + (size_t)li[li[b]] * 64 + (2 * p - 128);
            v0 = e[0]; v1 = e[1];
        }
        unsigned h, l;
        split_bf(v0, v1, h, l);
        cs[2 * idx] = h; cs[2 * idx + 1] = l;
    } else if (idx < n1 + n2) {
        int j = idx - n1;
        int b = j / (16 * 64);
        int rem = j - b * 16 * 64;
        int s = rem / 64, p = rem - s * 64;
        float v0, v1;
        if (p < 32) {
            const float* src = tagset + ((size_t)(b * 16 + s)) * 64 + 2 * p;
            v0 = src[0]; v1 = src[1];
        } else {
            const float* e = lang_embeds + (size_t)li[li[b]] * 64 + (2 * p - 64);
            v0 = e[0]; v1 = e[1];
        }
        unsigned h, l;
        split_bf(v0, v1, h, l);
        ts[2 * j] = h; ts[2 * j + 1] = l;
    }
}

__global__ void build_decin(const float* __restrict__ labels, unsigned* __restrict__ decin) {
    int idx = blockIdx.x * blockDim.x + threadIdx.x;   // pairs: 512*48*64
    if (idx >= 512 * 48 * 64) return;
    int t = (idx >> 6) % 48;
    float v0 = 0.f, v1 = 0.f;
    if (t != 0) { v0 = labels[2 * idx]; v1 = labels[2 * idx + 1]; }
    unsigned h, l;
    split_bf(v0, v1, h, l);
    decin[2 * idx] = h; decin[2 * idx + 1] = l;
}

// ---------------------------------------------------------------------------
// GEMM on packed operands. 128x128 tile, k-step 64, 512 thr, warp tile 32x32.
// A,W packed words [rows][K]. Epilogue: fp32 out (ES=false) or packed (true).
// smem stage: Ah[128*40] Al Bh Bl = 20480 words; double = 163840 B.
// ---------------------------------------------------------------------------
__device__ __forceinline__ void g_ldg(const unsigned* __restrict__ A,
                                      const unsigned* __restrict__ W,
                                      int K, int bm, int bn, int k0, int tid,
                                      uint4* av, uint4* wv) {
#pragma unroll
    for (int i = 0; i < 4; i++) {
        int idx = tid + i * 512;
        int row = idx >> 4, fc = idx & 15;
        av[i] = *(const uint4*)(A + (size_t)(bm + row) * K + k0 + fc * 4);
        wv[i] = *(const uint4*)(W + (size_t)(bn + row) * K + k0 + fc * 4);
    }
}

__device__ __forceinline__ void g_sts(unsigned* __restrict__ buf, int tid,
                                      const uint4* av, const uint4* wv) {
    unsigned* Ah = buf;
    unsigned* Al = buf + 5120;
    unsigned* Bh = buf + 10240;
    unsigned* Bl = buf + 15360;
#pragma unroll
    for (int i = 0; i < 4; i++) {
        int idx = tid + i * 512;
        int row = idx >> 4, fc = idx & 15;
        int pa = row * 40 + permk2(fc * 2);
        int pb = row * 40 + permk2(fc * 2 + 1);
        Ah[pa] = av[i].x; Al[pa] = av[i].y; Ah[pb] = av[i].z; Al[pb] = av[i].w;
        Bh[pa] = wv[i].x; Bl[pa] = wv[i].y; Bh[pb] = wv[i].z; Bl[pb] = wv[i].w;
    }
}

__device__ __forceinline__ void g_compute(const unsigned* __restrict__ buf,
                                          int wm, int wn, int gid, int tig,
                                          float (&acc)[2][4][4]) {
    const unsigned* Ah = buf;
    const unsigned* Al = buf + 5120;
    const unsigned* Bh = buf + 10240;
    const unsigned* Bl = buf + 15360;
#pragma unroll
    for (int s = 0; s < 4; s++) {
        unsigned ah[2][4], al[2][4];
#pragma unroll
        for (int mt = 0; mt < 2; mt++) {
            int o = (wm * 32 + mt * 16 + gid) * 40 + s * 8 + tig * 2;
            uint2 p = *(const uint2*)(Ah + o);
            uint2 q = *(const uint2*)(Ah + o + 320);
            ah[mt][0] = p.x; ah[mt][2] = p.y; ah[mt][1] = q.x; ah[mt][3] = q.y;
            uint2 r = *(const uint2*)(Al + o);
            uint2 t = *(const uint2*)(Al + o + 320);
            al[mt][0] = r.x; al[mt][2] = r.y; al[mt][1] = t.x; al[mt][3] = t.y;
        }
        unsigned bh[4][2], bl[4][2];
#pragma unroll
        for (int j = 0; j < 4; j++) {
            int o = (wn * 32 + j * 8 + gid) * 40 + s * 8 + tig * 2;
            uint2 p = *(const uint2*)(Bh + o);
            bh[j][0] = p.x; bh[j][1] = p.y;
            uint2 q = *(const uint2*)(Bl + o);
            bl[j][0] = q.x; bl[j][1] = q.y;
        }
#pragma unroll
        for (int mt = 0; mt < 2; mt++)
#pragma unroll
            for (int j = 0; j < 4; j++) {
                float* c = acc[mt][j];
                mma16bf(c, ah[mt], bh[j]);
                mma16bf(c, ah[mt], bl[j]);
                mma16bf(c, al[mt], bh[j]);
            }
    }
}

template<bool ES>
__global__ __launch_bounds__(512) void gemm_mma(
    const unsigned* __restrict__ A, const unsigned* __restrict__ W,
    const float* __restrict__ bias, void* __restrict__ Cv,
    int M, int N, int K, int ldc)
{
    extern __shared__ unsigned gsb[];
    unsigned* bufs[2] = { gsb, gsb + 20480 };
    const int bm = blockIdx.y * 128;
    const int bn = blockIdx.x * 128;
    const int tid = threadIdx.x;
    const int wid = tid >> 5, lane = tid & 31;
    const int wm = wid >> 2, wn = wid & 3;
    const int gid = lane >> 2, tig = lane & 3;

    float acc[2][4][4];
#pragma unroll
    for (int i = 0; i < 2; i++)
#pragma unroll
        for (int j = 0; j < 4; j++)
#pragma unroll
            for (int r = 0; r < 4; r++) acc[i][j][r] = 0.f;

    const int NT = K >> 6;
    uint4 av[4], wv[4];

    g_ldg(A, W, K, bm, bn, 0, tid, av, wv);
    g_sts(bufs[0], tid, av, wv);
    __syncthreads();
    g_ldg(A, W, K, bm, bn, 64, tid, av, wv);

    for (int kt = 0; kt < NT; kt++) {
        if (kt + 1 < NT) g_sts(bufs[(kt + 1) & 1], tid, av, wv);
        if (kt + 2 < NT) g_ldg(A, W, K, bm, bn, (kt + 2) * 64, tid, av, wv);
        g_compute(bufs[kt & 1], wm, wn, gid, tig, acc);
        __syncthreads();
    }

#pragma unroll
    for (int mt = 0; mt < 2; mt++)
#pragma unroll
        for (int nt = 0; nt < 4; nt++) {
            int row = bm + wm * 32 + mt * 16 + gid;
            int col = bn + wn * 32 + nt * 8 + tig * 2;
            float b0 = bias[col], b1 = bias[col + 1];
            float* c = acc[mt][nt];
            float v00 = c[0] + b0, v01 = c[1] + b1;
            float v10 = c[2] + b0, v11 = c[3] + b1;
            if (ES) {
                unsigned* C = (unsigned*)Cv;
                unsigned h, l;
                split_bf(v00, v01, h, l);
                *(uint2*)(C + (size_t)row * ldc + col) = make_uint2(h, l);
                split_bf(v10, v11, h, l);
                *(uint2*)(C + (size_t)(row + 8) * ldc + col) = make_uint2(h, l);
            } else {
                float* C = (float*)Cv;
                float* p0 = C + (size_t)row * ldc + col;
                float* p1 = C + (size_t)(row + 8) * ldc + col;
                p0[0] = v00; p0[1] = v01;
                p1[0] = v10; p1[1] = v11;
            }
        }
}

// ---------------------------------------------------------------------------
// Persistent LSTM (bf16x3), packed h/W operands, k-step 64, group barriers.
// Block tile: BM=32 batch x 64 j x 4 gates, 16 warps, warp N=16.
// smem stage: Ah[32*40] Al Bh[256*40] Bl = 23040 words; double = 184320 B.
// ---------------------------------------------------------------------------
struct PChain {
    const float*    xg0;  long dxg;
    unsigned*       ho0;  long dho;     // packed h
    const unsigned* hp_init;            // packed (nullptr => zeros)
    const float*    cp_init;
    const unsigned* whh;                // packed [4H][H words]
    float*          cbuf;
    int ldx, ldh, ldo, ldh_init;
};
struct PArgs { PChain c[2]; };

__device__ __forceinline__ float sigm(float x) { return 1.f / (1.f + expf(-x)); }

template<int BM>
__device__ __forceinline__ void l_ldg(const unsigned* hp, int ldh,
                                      const unsigned* whh,
                                      int H, int b0, int j0, int k0, int tid,
                                      uint4* av, uint4* wv) {
    {
        int r = tid >> 4, fc = tid & 15;
        av[0] = *(const uint4*)(hp + (size_t)(b0 + r) * ldh + k0 + fc * 4);
    }
#pragma unroll
    for (int i = 0; i < 8; i++) {
        int idx = tid + i * 512;
        int r = idx >> 4, fc = idx & 15;
        int g = r >> 6, jl = r & 63;
        wv[i] = *(const uint4*)(whh + (size_t)(g * H + j0 + jl) * H + k0 + fc * 4);
    }
}

template<int BM>
__device__ __forceinline__ void l_sts(unsigned* __restrict__ buf, int tid,
                                      const uint4* av, const uint4* wv) {
    unsigned* Ah = buf;
    unsigned* Al = buf + BM * 40;
    unsigned* Bh = buf + 2 * BM * 40;
    unsigned* Bl = buf + 2 * BM * 40 + 10240;
    {
        int r = tid >> 4, fc = tid & 15;
        int pa = r * 40 + permk2(fc * 2);
        int pb = r * 40 + permk2(fc * 2 + 1);
        Ah[pa] = av[0].x; Al[pa] = av[0].y; Ah[pb] = av[0].z; Al[pb] = av[0].w;
    }
#pragma unroll
    for (int i = 0; i < 8; i++) {
        int idx = tid + i * 512;
        int r = idx >> 4, fc = idx & 15;
        int pa = r * 40 + permk2(fc * 2);
        int pb = r * 40 + permk2(fc * 2 + 1);
        Bh[pa] = wv[i].x; Bl[pa] = wv[i].y; Bh[pb] = wv[i].z; Bl[pb] = wv[i].w;
    }
}

template<int BM>
__device__ __forceinline__ void l_compute(const unsigned* __restrict__ buf,
                                          int wn, int gid, int tig,
                                          float (&acc)[BM/16][2][4]) {
    constexpr int MT = BM / 16;
    const unsigned* Ah = buf;
    const unsigned* Al = buf + BM * 40;
    const unsigned* Bh = buf + 2 * BM * 40;
    const unsigned* Bl = buf + 2 * BM * 40 + 10240;
#pragma unroll
    for (int s = 0; s < 4; s++) {
        unsigned ah[MT][4], al[MT][4];
#pragma unroll
        for (int mt = 0; mt < MT; mt++) {
            int o = (mt * 16 + gid) * 40 + s * 8 + tig * 2;
            uint2 p = *(const uint2*)(Ah + o);
            uint2 q = *(const uint2*)(Ah + o + 320);
            ah[mt][0] = p.x; ah[mt][2] = p.y; ah[mt][1] = q.x; ah[mt][3] = q.y;
            uint2 r = *(const uint2*)(Al + o);
            uint2 t = *(const uint2*)(Al + o + 320);
            al[mt][0] = r.x; al[mt][2] = r.y; al[mt][1] = t.x; al[mt][3] = t.y;
        }
        unsigned bh[2][2], bl[2][2];
#pragma unroll
        for (int nj = 0; nj < 2; nj++) {
            int o = (wn * 16 + nj * 8 + gid) * 40 + s * 8 + tig * 2;
            uint2 p = *(const uint2*)(Bh + o);
            bh[nj][0] = p.x; bh[nj][1] = p.y;
            uint2 q = *(const uint2*)(Bl + o);
            bl[nj][0] = q.x; bl[nj][1] = q.y;
        }
#pragma unroll
        for (int mt = 0; mt < MT; mt++)
#pragma unroll
            for (int nj = 0; nj < 2; nj++) {
                float* c = acc[mt][nj];
                mma16bf(c, ah[mt], bh[nj]);
                mma16bf(c, ah[mt], bl[nj]);
                mma16bf(c, al[mt], bh[nj]);
            }
    }
}

template<int BM>
__device__ void lstm_body(const float* Xg, const unsigned* hp, const float* cp,
                          const unsigned* whh, unsigned* ho, float* co,
                          int ldx, int ldh, int ldo, int H,
                          unsigned* sb, int j0, int b0, int tid) {
    constexpr int MT = BM / 16;
    constexpr int BUFSZ = (2 * BM + 512) * 40;
    unsigned* bufs[2] = { sb, sb + BUFSZ };
    const int lane = tid & 31;
    const int wn = tid >> 5;
    const int gid = lane >> 2, tig = lane & 3;

    if (hp) {
        float acc[MT][2][4];
#pragma unroll
        for (int mt = 0; mt < MT; mt++)
#pragma unroll
            for (int nj = 0; nj < 2; nj++)
#pragma unroll
                for (int r = 0; r < 4; r++) acc[mt][nj][r] = 0.f;

        const int NKT = H >> 6;
        uint4 av[1], wv[8];

        l_ldg<BM>(hp, ldh, whh, H, b0, j0, 0, tid, av, wv);
        l_sts<BM>(bufs[0], tid, av, wv);
        __syncthreads();
        l_ldg<BM>(hp, ldh, whh, H, b0, j0, 64, tid, av, wv);

        for (int kt = 0; kt < NKT; kt++) {
            if (kt + 1 < NKT) l_sts<BM>(bufs[(kt + 1) & 1], tid, av, wv);
            if (kt + 2 < NKT) l_ldg<BM>(hp, ldh, whh, H, b0, j0, (kt + 2) * 64, tid, av, wv);
            l_compute<BM>(bufs[kt & 1], wn, gid, tig, acc);
            __syncthreads();
        }

        // gate exchange: EB[b_local][flat_col], stride 260 (floats)
        float* EB = (float*)sb;
#pragma unroll
        for (int mt = 0; mt < MT; mt++)
#pragma unroll
            for (int nj = 0; nj < 2; nj++) {
                int col = wn * 16 + nj * 8 + tig * 2;
                float* c = acc[mt][nj];
                EB[(mt * 16 + gid) * 260 + col]         = c[0];
                EB[(mt * 16 + gid) * 260 + col + 1]     = c[1];
                EB[(mt * 16 + gid + 8) * 260 + col]     = c[2];
                EB[(mt * 16 + gid + 8) * 260 + col + 1] = c[3];
            }
        __syncthreads();
    }

    // epilogue: each thread handles a j-pair; writes packed h (uint2) + fp32 c
    const float* EB = (const float*)sb;
    const int jp = tid & 31;          // pair index, j = j0 + 2*jp
    const int row0 = tid >> 5;        // 0..15
#pragma unroll
    for (int pass = 0; pass < BM / 16; pass++) {
        int bl_ = row0 + pass * 16;
        int b = b0 + bl_;
        const float* xr = Xg + (size_t)b * ldx;
        int j = j0 + 2 * jp;
        float2 a0 = {0.f, 0.f}, a1 = a0, a2 = a0, a3 = a0;
        if (hp) {
            const float* eb = EB + bl_ * 260 + 2 * jp;
            a0 = *(const float2*)(eb);
            a1 = *(const float2*)(eb + 64);
            a2 = *(const float2*)(eb + 128);
            a3 = *(const float2*)(eb + 192);
        }
        float2 xi = *(const float2*)(xr + j);
        float2 xf = *(const float2*)(xr + H + j);
        float2 xg = *(const float2*)(xr + 2 * H + j);
        float2 xo = *(const float2*)(xr + 3 * H + j);
        float2 cpv = {0.f, 0.f};
        if (cp) cpv = *(const float2*)(cp + (size_t)b * H + j);
        float cc0 = sigm(a1.x + xf.x) * cpv.x + sigm(a0.x + xi.x) * tanhf(a2.x + xg.x);
        float cc1 = sigm(a1.y + xf.y) * cpv.y + sigm(a0.y + xi.y) * tanhf(a2.y + xg.y);
        float h0f = sigm(a3.x + xo.x) * tanhf(cc0);
        float h1f = sigm(a3.y + xo.y) * tanhf(cc1);
        *(float2*)(co + (size_t)b * H + j) = make_float2(cc0, cc1);
        unsigned hh, hl;
        split_bf(h0f, h1f, hh, hl);
        *(uint2*)(ho + (size_t)b * ldo + j) = make_uint2(hh, hl);
    }
}

template<int BM>
__global__ __launch_bounds__(512) void lstm_persist(PArgs pa, int H, int nsteps) {
    extern __shared__ unsigned lsb[];
    const PChain ch = pa.c[blockIdx.z];
    const int j0 = blockIdx.x * 64;
    const int b0 = blockIdx.y * BM;
    const int tid = threadIdx.x;
    const size_t CB = 512 * (size_t)H;
    const int grp = blockIdx.z * gridDim.y + blockIdx.y;
    const unsigned nblk = gridDim.x;

    for (int t = 0; t < nsteps; t++) {
        const float* Xg = ch.xg0 + (long)t * ch.dxg;
        const unsigned* hp;
        const float* cp;
        int ldh;
        if (t == 0) { hp = ch.hp_init; cp = ch.cp_init; ldh = ch.ldh_init; }
        else {
            hp = ch.ho0 + (long)(t - 1) * ch.dho;
            cp = ch.cbuf + (size_t)(t & 1) * CB;
            ldh = ch.ldh;
        }
        unsigned* ho = ch.ho0 + (long)t * ch.dho;
        float* co = ch.cbuf + (size_t)((t + 1) & 1) * CB;

        lstm_body<BM>(Xg, hp, cp, ch.whh, ho, co,
                      ch.ldx, ldh, ch.ldo, H, lsb, j0, b0, tid);
        if (t + 1 < nsteps) group_barrier(grp, nblk);
    }
}

__global__ void build_h0c0(const unsigned* __restrict__ COw, const unsigned* __restrict__ TOw,
                           const float* __restrict__ ccf, const float* __restrict__ ctf,
                           unsigned* __restrict__ h0, float* __restrict__ c0) {
    int idx = blockIdx.x * blockDim.x + threadIdx.x;
    if (idx >= 512 * 512) return;
    int b = idx >> 9, w = idx & 511;
    // h0 word copy (packed in, packed out)
    unsigned hv;
    if (w < 256) hv = COw[((size_t)b * 48 + 47) * 512 + w];
    else         hv = TOw[((size_t)b * 16 + 15) * 512 + (w - 256)];
    h0[idx] = hv;
    // c0 value copy (fp32)
    float cv;
    if (w < 256) cv = ccf[b * 256 + w];
    else         cv = ctf[b * 256 + (w - 256)];
    c0[idx] = cv;
}

// ---------------------------------------------------------------------------
// Single-head attention; fp32 in, PACKED out.
// ---------------------------------------------------------------------------
__global__ __launch_bounds__(256) void attn_kernel(
    const float* __restrict__ Q, const float* __restrict__ KV,
    unsigned* __restrict__ O, int Lk)
{
    const int b = blockIdx.x;
    const int tid = threadIdx.x;
    __shared__ float Qs[48][68];
    __shared__ float Ks[48][68];
    __shared__ float s[48][48];

    const float* Qb = Q + (size_t)b * 48 * 512;
    const float* Kb = KV + (size_t)b * Lk * 1024;

    float acc[9];
#pragma unroll
    for (int i = 0; i < 9; i++) acc[i] = 0.f;

    for (int e0 = 0; e0 < 512; e0 += 64) {
        __syncthreads();
        for (int idx = tid; idx < 48 * 16; idx += 256) {
            int r = idx >> 4, cc = (idx & 15) << 2;
            *(float4*)&Qs[r][cc] = *(const float4*)(Qb + (size_t)r * 512 + e0 + cc);
        }
        for (int idx = tid; idx < Lk * 16; idx += 256) {
            int r = idx >> 4, cc = (idx & 15) << 2;
            *(float4*)&Ks[r][cc] = *(const float4*)(Kb + (size_t)r * 1024 + e0 + cc);
        }
        __syncthreads();
        int pi = 0;
        for (int idx = tid; idx < 48 * Lk; idx += 256, pi++) {
            int q = idx / Lk, k = idx - q * Lk;
            float sum = 0.f;
#pragma unroll 16
            for (int e = 0; e < 64; e++) sum += Qs[q][e] * Ks[k][e];
            acc[pi] += sum;
        }
    }
    __syncthreads();
    {
        const float scale = 0.04419417382415922f;   // 1/sqrt(512)
        int pi = 0;
        for (int idx = tid; idx < 48 * Lk; idx += 256, pi++) {
            int q = idx / Lk, k = idx - q * Lk;
            s[q][k] = acc[pi] * scale;
        }
    }
    __syncthreads();
    if (tid < 48) {
        float m = -1e30f;
        for (int k = 0; k < Lk; k++) m = fmaxf(m, s[tid][k]);
        float sum = 0.f;
        for (int k = 0; k < Lk; k++) { float e = expf(s[tid][k] - m); s[tid][k] = e; sum += e; }
        float inv = 1.f / sum;
        for (int k = 0; k < Lk; k++) s[tid][k] *= inv;
    }
    __syncthreads();

    unsigned* Ob = O + (size_t)b * 48 * 512;
    const float* Vb = KV + (size_t)b * Lk * 1024 + 512;
    for (int e0 = 0; e0 < 512; e0 += 64) {
        for (int idx = tid; idx < Lk * 16; idx += 256) {
            int r = idx >> 4, cc = (idx & 15) << 2;
            *(float4*)&Ks[r][cc] = *(const float4*)(Vb + (size_t)r * 1024 + e0 + cc);
        }
        __syncthreads();
        for (int idx = tid; idx < 48 * 32; idx += 256) {
            int q = idx >> 5, ep = idx & 31;
            int e = 2 * ep;
            float s0 = 0.f, s1 = 0.f;
            for (int k = 0; k < Lk; k++) {
                float w = s[q][k];
                s0 += w * Ks[k][e];
                s1 += w * Ks[k][e + 1];
            }
            unsigned h, l;
            split_bf(s0, s1, h, l);
            *(uint2*)(Ob + (size_t)q * 512 + e0 + e) = make_uint2(h, l);
        }
        __syncthreads();
    }
}

// ---------------------------------------------------------------------------
// Exact 1.5-entmax via warp bisection; one warp per row of 128.
// ---------------------------------------------------------------------------
__global__ __launch_bounds__(256) void entmax_kernel(
    const float* __restrict__ logits, float* __restrict__ out, int nrows)
{
    int row = blockIdx.x * 8 + (threadIdx.x >> 5);
    if (row >= nrows) return;
    int lane = threadIdx.x & 31;
    const float* x = logits + (size_t)row * 128;
    float z[4];
    float m = -1e30f;
#pragma unroll
    for (int i = 0; i < 4; i++) { z[i] = x[lane + 32 * i] * 0.5f; m = fmaxf(m, z[i]); }
#pragma unroll
    for (int o = 16; o; o >>= 1) m = fmaxf(m, __shfl_xor_sync(0xffffffffu, m, o));
#pragma unroll
    for (int i = 0; i < 4; i++) z[i] -= m;
    float lo = -1.f, hi = 0.f;
    for (int it = 0; it < 35; it++) {
        float tau = 0.5f * (lo + hi);
        float f = 0.f;
#pragma unroll
        for (int i = 0; i < 4; i++) { float d = fmaxf(z[i] - tau, 0.f); f += d * d; }
#pragma unroll
        for (int o = 16; o; o >>= 1) f += __shfl_xor_sync(0xffffffffu, f, o);
        if (f >= 1.f) lo = tau; else hi = tau;
    }
    float tau = 0.5f * (lo + hi);
    float* yo = out + (size_t)row * 128;
#pragma unroll
    for (int i = 0; i < 4; i++) { float d = fmaxf(z[i] - tau, 0.f); yo[lane + 32 * i] = d * d; }
}

// ---------------------------------------------------------------------------
extern "C" void kernel_launch(void* const* d_in, const int* in_sizes, int n_in,
                              void* d_out, int out_size) {
    const int*   li          = (const int*)  d_in[0];
    const float* char_seq    = (const float*)d_in[1];
    const float* tagset      = (const float*)d_in[2];
    const float* labels      = (const float*)d_in[3];
    const float* lang_embeds = (const float*)d_in[4];
    const float* c_w_ih_f    = (const float*)d_in[5];
    const float* c_w_hh_f    = (const float*)d_in[6];
    const float* c_b_f       = (const float*)d_in[7];
    const float* c_w_ih_b    = (const float*)d_in[8];
    const float* c_w_hh_b    = (const float*)d_in[9];
    const float* c_b_b       = (const float*)d_in[10];
    const float* t_w_ih_f    = (const float*)d_in[11];
    const float* t_w_hh_f    = (const float*)d_in[12];
    const float* t_b_f       = (const float*)d_in[13];
    const float* t_w_ih_b    = (const float*)d_in[14];
    const float* t_w_hh_b    = (const float*)d_in[15];
    const float* t_b_b       = (const float*)d_in[16];
    const float* cell_w_ih   = (const float*)d_in[17];
    const float* cell_w_hh   = (const float*)d_in[18];
    const float* cell_b      = (const float*)d_in[19];
    const float* ch_in_w     = (const float*)d_in[20];
    const float* ch_in_b     = (const float*)d_in[21];
    const float* ch_out_w    = (const float*)d_in[22];
    const float* ch_out_b    = (const float*)d_in[23];
    const float* tg_in_w     = (const float*)d_in[24];
    const float* tg_in_b     = (const float*)d_in[25];
    const float* tg_out_w    = (const float*)d_in[26];
    const float* tg_out_b    = (const float*)d_in[27];
    const float* fc_w        = (const float*)d_in[28];
    const float* fc_b        = (const float*)d_in[29];
    float* OUT = (float*)d_out;

    float* S = nullptr;
    cudaGetSymbolAddress((void**)&S, g_scratch);

    unsigned* CSw   = (unsigned*)(S + O_CS);
    unsigned* TSw   = (unsigned*)(S + O_TS);
    unsigned* DIw   = (unsigned*)(S + O_DECIN);
    unsigned* COw   = (unsigned*)(S + O_CO);
    unsigned* TOw   = (unsigned*)(S + O_TO);
    unsigned* HSw   = (unsigned*)(S + O_HS);
    unsigned* H0w   = (unsigned*)(S + O_H0);
    unsigned* OCw   = (unsigned*)(S + O_OC);
    unsigned* OTw   = (unsigned*)(S + O_OT);
    unsigned* CATw  = (unsigned*)(S + O_CAT);
    unsigned* PCIF  = (unsigned*)(S + O_PCIF);
    unsigned* PCIB  = (unsigned*)(S + O_PCIB);
    unsigned* PTIF  = (unsigned*)(S + O_PTIF);
    unsigned* PTIB  = (unsigned*)(S + O_PTIB);
    unsigned* PDI   = (unsigned*)(S + O_PDI);
    unsigned* PCHI  = (unsigned*)(S + O_PCHI);
    unsigned* PTGI  = (unsigned*)(S + O_PTGI);
    unsigned* PCHO  = (unsigned*)(S + O_PCHO);
    unsigned* PTGO  = (unsigned*)(S + O_PTGO);
    unsigned* PFC   = (unsigned*)(S + O_PFC);
    unsigned* PCHF  = (unsigned*)(S + O_PCHF);
    unsigned* PCHB  = (unsigned*)(S + O_PCHB);
    unsigned* PTHF  = (unsigned*)(S + O_PTHF);
    unsigned* PTHB  = (unsigned*)(S + O_PTHB);
    unsigned* PDHH  = (unsigned*)(S + O_PDHH);

    const int GSM = 163840;
    const int LSM = 184320;
    static bool attr_set = false;
    if (!attr_set) {
        cudaFuncSetAttribute(gemm_mma<false>, cudaFuncAttributeMaxDynamicSharedMemorySize, GSM);
        cudaFuncSetAttribute(gemm_mma<true>,  cudaFuncAttributeMaxDynamicSharedMemorySize, GSM);
        cudaFuncSetAttribute(lstm_persist<32>, cudaFuncAttributeMaxDynamicSharedMemorySize, LSM);
        attr_set = true;
    }

    // 1) input prep (packed) + weight packing
    prep_kernel<<<CDIV(2883584, 256), 256>>>(li, char_seq, tagset, lang_embeds, CSw, TSw);
    build_decin<<<CDIV(1572864, 256), 256>>>(labels, DIw);
    wsplit_pack<<<CDIV(98304, 256), 256>>>(c_w_ih_f, PCIF, 98304);
    wsplit_pack<<<CDIV(98304, 256), 256>>>(c_w_ih_b, PCIB, 98304);
    wsplit_pack<<<CDIV(65536, 256), 256>>>(t_w_ih_f, PTIF, 65536);
    wsplit_pack<<<CDIV(65536, 256), 256>>>(t_w_ih_b, PTIB, 65536);
    wsplit_pack<<<CDIV(131072, 256), 256>>>(cell_w_ih, PDI, 131072);
    wsplit_pack<<<CDIV(393216, 256), 256>>>(ch_in_w, PCHI, 393216);
    wsplit_pack<<<CDIV(393216, 256), 256>>>(tg_in_w, PTGI, 393216);
    wsplit_pack<<<CDIV(131072, 256), 256>>>(ch_out_w, PCHO, 131072);
    wsplit_pack<<<CDIV(131072, 256), 256>>>(tg_out_w, PTGO, 131072);
    wsplit_pack<<<CDIV(65536, 256), 256>>>(fc_w, PFC, 65536);
    wsplit_pack<<<CDIV(131072, 256), 256>>>(c_w_hh_f, PCHF, 131072);
    wsplit_pack<<<CDIV(131072, 256), 256>>>(c_w_hh_b, PCHB, 131072);
    wsplit_pack<<<CDIV(131072, 256), 256>>>(t_w_hh_f, PTHF, 131072);
    wsplit_pack<<<CDIV(131072, 256), 256>>>(t_w_hh_b, PTHB, 131072);
    wsplit_pack<<<CDIV(524288, 256), 256>>>(cell_w_hh, PDHH, 524288);

    // 2) input-projection GEMMs (fp32 outputs)
    gemm_mma<false><<<dim3(8, 192), 512, GSM>>>(CSw, PCIF, c_b_f, S + O_XCF, 24576, 1024, 192, 1024);
    gemm_mma<false><<<dim3(8, 192), 512, GSM>>>(CSw, PCIB, c_b_b, S + O_XCB, 24576, 1024, 192, 1024);
    gemm_mma<false><<<dim3(8,  64), 512, GSM>>>(TSw, PTIF, t_b_f, S + O_XTF,  8192, 1024, 128, 1024);
    gemm_mma<false><<<dim3(8,  64), 512, GSM>>>(TSw, PTIB, t_b_b, S + O_XTB,  8192, 1024, 128, 1024);
    gemm_mma<false><<<dim3(16,192), 512, GSM>>>(DIw, PDI, cell_b, S + O_XDEC, 24576, 2048, 128, 2048);

    // 3) encoder recurrences
    {
        PArgs A;
        A.c[0] = { S + O_XCF, 1024, COw, 512,
                   nullptr, nullptr, PCHF, S + O_CCF,
                   48 * 1024, 48 * 512, 48 * 512, 0 };
        A.c[1] = { S + O_XCB + 47ll * 1024, -1024, COw + 47ll * 512 + 256, -512,
                   nullptr, nullptr, PCHB, S + O_CCB,
                   48 * 1024, 48 * 512, 48 * 512, 0 };
        lstm_persist<32><<<dim3(4, 16, 2), 512, LSM>>>(A, 256, 48);

        PArgs T;
        T.c[0] = { S + O_XTF, 1024, TOw, 512,
                   nullptr, nullptr, PTHF, S + O_CTF,
                   16 * 1024, 16 * 512, 16 * 512, 0 };
        T.c[1] = { S + O_XTB + 15ll * 1024, -1024, TOw + 15ll * 512 + 256, -512,
                   nullptr, nullptr, PTHB, S + O_CTB,
                   16 * 1024, 16 * 512, 16 * 512, 0 };
        lstm_persist<32><<<dim3(4, 16, 2), 512, LSM>>>(T, 256, 16);
    }

    // 4) initial decoder state (packed h0, fp32 c0)
    build_h0c0<<<1024, 256>>>(COw, TOw, S + O_CCF, S + O_CTF, H0w, S + O_C0);

    // 5) decoder recurrence
    {
        PArgs D;
        D.c[0] = { S + O_XDEC, 2048, HSw, 512,
                   H0w, S + O_C0, PDHH, S + O_DC,
                   48 * 2048, 48 * 512, 48 * 512, 512 };
        D.c[1] = D.c[0];
        lstm_persist<32><<<dim3(8, 16, 1), 512, LSM>>>(D, 512, 48);
    }

    // 6) attention projections (packed A, fp32 outputs)
    gemm_mma<false><<<dim3(4, 192), 512, GSM>>>(HSw, PCHI, ch_in_b, S + O_QC, 24576, 512, 512, 512);
    gemm_mma<false><<<dim3(4, 192), 512, GSM>>>(HSw, PTGI, tg_in_b, S + O_QT, 24576, 512, 512, 512);
    gemm_mma<false><<<dim3(8, 192), 512, GSM>>>(COw, PCHI + 512 * 512, ch_in_b + 512,
                                                S + O_KVC, 24576, 1024, 512, 1024);
    gemm_mma<false><<<dim3(8,  64), 512, GSM>>>(TOw, PTGI + 512 * 512, tg_in_b + 512,
                                                S + O_KVT,  8192, 1024, 512, 1024);

    // 7) attention cores (packed outputs)
    attn_kernel<<<512, 256>>>(S + O_QC, S + O_KVC, OCw, 48);
    attn_kernel<<<512, 256>>>(S + O_QT, S + O_KVT, OTw, 16);

    // 8) output projections into packed concat buffer
    gemm_mma<true><<<dim3(4, 192), 512, GSM>>>(OCw, PCHO, ch_out_b, CATw,       24576, 512, 512, 1024);
    gemm_mma<true><<<dim3(4, 192), 512, GSM>>>(OTw, PTGO, tg_out_b, CATw + 512, 24576, 512, 512, 1024);

    // 9) final FC + entmax15
    gemm_mma<false><<<dim3(1, 192), 512, GSM>>>(CATw, PFC, fc_b, S + O_LOG, 24576, 128, 1024, 128);
    entmax_kernel<<<3072, 256>>>(S + O_LOG, OUT, 24576);
}

// round 17
// speedup vs baseline: 1.1703x; 1.0570x over previous
#include <cuda_runtime.h>
#include <cuda_bf16.h>
#include <math.h>

#define CDIV(a,b) (((a)+(b)-1)/(b))

// Dimensions: B=512, SC=48, ST=16, E=512, H=256, N_CHARS=128, N_TAGS=64
constexpr size_t SZ(size_t n) { return (n + 255) & ~(size_t)255; }

// Packed format: word[2p] = bf16x2(hi of v[2p],v[2p+1]), word[2p+1] = bf16x2(lo).
constexpr size_t O_CS    = 0;                                    // packed [24576][192]
constexpr size_t O_TS    = O_CS    + SZ(24576ull*192);           // packed [8192][128]
constexpr size_t O_DECIN = O_TS    + SZ(8192ull*128);            // packed [24576][128]
constexpr size_t O_XCF   = O_DECIN + SZ(24576ull*128);           // fp32 [24576][1024]
constexpr size_t O_XCB   = O_XCF   + SZ(24576ull*1024);
constexpr size_t O_XTF   = O_XCB   + SZ(24576ull*1024);          // fp32 [8192][1024]
constexpr size_t O_XTB   = O_XTF   + SZ(8192ull*1024);
constexpr size_t O_XDEC  = O_XTB   + SZ(8192ull*1024);           // fp32 [24576][2048]
constexpr size_t O_CO    = O_XDEC  + SZ(24576ull*2048);          // packed [24576][512]
constexpr size_t O_TO    = O_CO    + SZ(24576ull*512);           // packed [8192][512]
constexpr size_t O_HS    = O_TO    + SZ(8192ull*512);            // packed [24576][512]
constexpr size_t O_CCF   = O_HS    + SZ(24576ull*512);           // fp32 2x[512,256]
constexpr size_t O_CCB   = O_CCF   + SZ(2ull*512*256);
constexpr size_t O_CTF   = O_CCB   + SZ(2ull*512*256);
constexpr size_t O_CTB   = O_CTF   + SZ(2ull*512*256);
constexpr size_t O_DC    = O_CTB   + SZ(2ull*512*256);           // fp32 2x[512,512]
constexpr size_t O_H0    = O_DC    + SZ(2ull*512*512);           // packed [512][512]
constexpr size_t O_C0    = O_H0    + SZ(512ull*512);             // fp32 [512][512]
constexpr size_t O_QC    = O_C0    + SZ(512ull*512);             // fp32 [24576][512]
constexpr size_t O_QT    = O_QC    + SZ(24576ull*512);
constexpr size_t O_KVC   = O_QT    + SZ(24576ull*512);           // fp32 [24576][1024]
constexpr size_t O_KVT   = O_KVC   + SZ(24576ull*1024);          // fp32 [8192][1024]
constexpr size_t O_OC    = O_KVT   + SZ(8192ull*1024);           // packed [24576][512]
constexpr size_t O_OT    = O_OC    + SZ(24576ull*512);
constexpr size_t O_CAT   = O_OT    + SZ(24576ull*512);           // packed [24576][1024]
constexpr size_t O_LOG   = O_CAT   + SZ(24576ull*1024);          // fp32 [24576][128]
// packed weights
constexpr size_t O_PCIF  = O_LOG   + SZ(24576ull*128);
constexpr size_t O_PCIB  = O_PCIF  + SZ(196608);
constexpr size_t O_PTIF  = O_PCIB  + SZ(196608);
constexpr size_t O_PTIB  = O_PTIF  + SZ(131072);
constexpr size_t O_PDI   = O_PTIB  + SZ(131072);
constexpr size_t O_PCHI  = O_PDI   + SZ(262144);
constexpr size_t O_PTGI  = O_PCHI  + SZ(786432);
constexpr size_t O_PCHO  = O_PTGI  + SZ(786432);
constexpr size_t O_PTGO  = O_PCHO  + SZ(262144);
constexpr size_t O_PFC   = O_PTGO  + SZ(262144);
constexpr size_t O_PCHF  = O_PFC   + SZ(131072);
constexpr size_t O_PCHB  = O_PCHF  + SZ(262144);
constexpr size_t O_PTHF  = O_PCHB  + SZ(262144);
constexpr size_t O_PTHB  = O_PTHF  + SZ(262144);
constexpr size_t O_PDHH  = O_PTHB  + SZ(262144);
constexpr size_t O_END   = O_PDHH  + SZ(1048576);

__device__ float g_scratch[O_END];

// ---------------------------------------------------------------------------
// group-local barriers
// ---------------------------------------------------------------------------
__device__ unsigned g_gcnt[64 * 32];
__device__ unsigned g_ggen[64 * 32];

__device__ __forceinline__ void group_barrier(int gid, unsigned nblk) {
    __syncthreads();
    __threadfence();
    if (threadIdx.x == 0) {
        volatile unsigned* vg = &g_ggen[gid * 32];
        unsigned my = *vg;
        if (atomicInc(&g_gcnt[gid * 32], nblk - 1u) == nblk - 1u) {
            atomicAdd(&g_ggen[gid * 32], 1u);
        } else {
            while (*vg == my) __nanosleep(32);
        }
    }
    __syncthreads();
}

// ---------------------------------------------------------------------------
// bf16x3 helpers
// ---------------------------------------------------------------------------
__device__ __forceinline__ void split_bf(float x0, float x1,
                                         unsigned& hi2, unsigned& lo2) {
    unsigned h;
    asm("cvt.rn.bf16x2.f32 %0, %1, %2;" : "=r"(h) : "f"(x1), "f"(x0));
    float h0 = __uint_as_float(h << 16);
    float h1 = __uint_as_float(h & 0xffff0000u);
    float l0 = x0 - h0;
    float l1 = x1 - h1;
    unsigned l;
    asm("cvt.rn.bf16x2.f32 %0, %1, %2;" : "=r"(l) : "f"(l1), "f"(l0));
    hi2 = h; lo2 = l;
}

__device__ __forceinline__ void mma16bf(float* c, const unsigned* a, const unsigned* b) {
    asm volatile(
        "mma.sync.aligned.m16n8k16.row.col.f32.bf16.bf16.f32 "
        "{%0,%1,%2,%3}, {%4,%5,%6,%7}, {%8,%9}, {%0,%1,%2,%3};\n"
        : "+f"(c[0]), "+f"(c[1]), "+f"(c[2]), "+f"(c[3])
        : "r"(a[0]), "r"(a[1]), "r"(a[2]), "r"(a[3]), "r"(b[0]), "r"(b[1]));
}

__device__ __forceinline__ int permk2(int k2) {
    return (k2 >> 3) * 8 + (k2 & 3) * 2 + ((k2 >> 2) & 1);
}

// ---------------------------------------------------------------------------
// one fused weight-packing kernel (15 jobs)
// ---------------------------------------------------------------------------
struct WJobs {
    const float* src[15];
    unsigned*    dst[15];
    int          end[15];   // inclusive-scan pair counts
};

__global__ void wsplit_all(WJobs J, int total) {
    int idx = blockIdx.x * blockDim.x + threadIdx.x;
    if (idx >= total) return;
    int j = 0;
    while (idx >= J.end[j]) j++;
    int start = j ? J.end[j - 1] : 0;
    int p = idx - start;
    unsigned h, l;
    split_bf(J.src[j][2 * p], J.src[j][2 * p + 1], h, l);
    J.dst[j][2 * p] = h;
    J.dst[j][2 * p + 1] = l;
}

// ---------------------------------------------------------------------------
// prep: emit packed cs / ts ; decin
// ---------------------------------------------------------------------------
__global__ void prep_kernel(const int* __restrict__ li,
                            const float* __restrict__ char_seq,
                            const float* __restrict__ tagset,
                            const float* __restrict__ lang_embeds,
                            unsigned* __restrict__ cs, unsigned* __restrict__ ts) {
    int idx = blockIdx.x * blockDim.x + threadIdx.x;
    const int n1 = 512 * 48 * 96;
    const int n2 = 512 * 16 * 64;
    if (idx < n1) {
        int b = idx / (48 * 96);
        int rem = idx - b * 48 * 96;
        int s = rem / 96, p = rem - s * 96;
        float v0, v1;
        if (p < 64) {
            const float* src = char_seq + ((size_t)(b * 48 + s)) * 128 + 2 * p;
            v0 = src[0]; v1 = src[1];
        } else {
            const float* e = lang_embeds + (size_t)li[li[b]] * 64 + (2 * p - 128);
            v0 = e[0]; v1 = e[1];
        }
        unsigned h, l;
        split_bf(v0, v1, h, l);
        cs[2 * idx] = h; cs[2 * idx + 1] = l;
    } else if (idx < n1 + n2) {
        int j = idx - n1;
        int b = j / (16 * 64);
        int rem = j - b * 16 * 64;
        int s = rem / 64, p = rem - s * 64;
        float v0, v1;
        if (p < 32) {
            const float* src = tagset + ((size_t)(b * 16 + s)) * 64 + 2 * p;
            v0 = src[0]; v1 = src[1];
        } else {
            const float* e = lang_embeds + (size_t)li[li[b]] * 64 + (2 * p - 64);
            v0 = e[0]; v1 = e[1];
        }
        unsigned h, l;
        split_bf(v0, v1, h, l);
        ts[2 * j] = h; ts[2 * j + 1] = l;
    }
}

__global__ void build_decin(const float* __restrict__ labels, unsigned* __restrict__ decin) {
    int idx = blockIdx.x * blockDim.x + threadIdx.x;
    if (idx >= 512 * 48 * 64) return;
    int t = (idx >> 6) % 48;
    float v0 = 0.f, v1 = 0.f;
    if (t != 0) { v0 = labels[2 * idx]; v1 = labels[2 * idx + 1]; }
    unsigned h, l;
    split_bf(v0, v1, h, l);
    decin[2 * idx] = h; decin[2 * idx + 1] = l;
}

// ---------------------------------------------------------------------------
// GEMM on packed operands; dual-job capable. 128x128 tile, k-step 64.
// ---------------------------------------------------------------------------
struct GemmDual {
    const unsigned* A0; const unsigned* W0; const float* bias0; void* C0;
    const unsigned* A1; const unsigned* W1; const float* bias1; void* C1;
    int nxa;
};

__device__ __forceinline__ void g_ldg(const unsigned* __restrict__ A,
                                      const unsigned* __restrict__ W,
                                      int K, int bm, int bn, int k0, int tid,
                                      uint4* av, uint4* wv) {
#pragma unroll
    for (int i = 0; i < 4; i++) {
        int idx = tid + i * 512;
        int row = idx >> 4, fc = idx & 15;
        av[i] = *(const uint4*)(A + (size_t)(bm + row) * K + k0 + fc * 4);
        wv[i] = *(const uint4*)(W + (size_t)(bn + row) * K + k0 + fc * 4);
    }
}

__device__ __forceinline__ void g_sts(unsigned* __restrict__ buf, int tid,
                                      const uint4* av, const uint4* wv) {
    unsigned* Ah = buf;
    unsigned* Al = buf + 5120;
    unsigned* Bh = buf + 10240;
    unsigned* Bl = buf + 15360;
#pragma unroll
    for (int i = 0; i < 4; i++) {
        int idx = tid + i * 512;
        int row = idx >> 4, fc = idx & 15;
        int pa = row * 40 + permk2(fc * 2);
        int pb = row * 40 + permk2(fc * 2 + 1);
        Ah[pa] = av[i].x; Al[pa] = av[i].y; Ah[pb] = av[i].z; Al[pb] = av[i].w;
        Bh[pa] = wv[i].x; Bl[pa] = wv[i].y; Bh[pb] = wv[i].z; Bl[pb] = wv[i].w;
    }
}

__device__ __forceinline__ void g_compute(const unsigned* __restrict__ buf,
                                          int wm, int wn, int gid, int tig,
                                          float (&acc)[2][4][4]) {
    const unsigned* Ah = buf;
    const unsigned* Al = buf + 5120;
    const unsigned* Bh = buf + 10240;
    const unsigned* Bl = buf + 15360;
#pragma unroll
    for (int s = 0; s < 4; s++) {
        unsigned ah[2][4], al[2][4];
#pragma unroll
        for (int mt = 0; mt < 2; mt++) {
            int o = (wm * 32 + mt * 16 + gid) * 40 + s * 8 + tig * 2;
            uint2 p = *(const uint2*)(Ah + o);
            uint2 q = *(const uint2*)(Ah + o + 320);
            ah[mt][0] = p.x; ah[mt][2] = p.y; ah[mt][1] = q.x; ah[mt][3] = q.y;
            uint2 r = *(const uint2*)(Al + o);
            uint2 t = *(const uint2*)(Al + o + 320);
            al[mt][0] = r.x; al[mt][2] = r.y; al[mt][1] = t.x; al[mt][3] = t.y;
        }
        unsigned bh[4][2], bl[4][2];
#pragma unroll
        for (int j = 0; j < 4; j++) {
            int o = (wn * 32 + j * 8 + gid) * 40 + s * 8 + tig * 2;
            uint2 p = *(const uint2*)(Bh + o);
            bh[j][0] = p.x; bh[j][1] = p.y;
            uint2 q = *(const uint2*)(Bl + o);
            bl[j][0] = q.x; bl[j][1] = q.y;
        }
#pragma unroll
        for (int mt = 0; mt < 2; mt++)
#pragma unroll
            for (int j = 0; j < 4; j++) {
                float* c = acc[mt][j];
                mma16bf(c, ah[mt], bh[j]);
                mma16bf(c, ah[mt], bl[j]);
                mma16bf(c, al[mt], bh[j]);
            }
    }
}

template<bool ES>
__global__ __launch_bounds__(512) void gemm_mma(
    GemmDual P, int M, int N, int K, int ldc)
{
    extern __shared__ unsigned gsb[];
    unsigned* bufs[2] = { gsb, gsb + 20480 };
    const unsigned* A; const unsigned* W; const float* bias; void* Cv;
    int bxn;
    if ((int)blockIdx.x < P.nxa) { A = P.A0; W = P.W0; bias = P.bias0; Cv = P.C0; bxn = blockIdx.x; }
    else { A = P.A1; W = P.W1; bias = P.bias1; Cv = P.C1; bxn = blockIdx.x - P.nxa; }
    const int bm = blockIdx.y * 128;
    const int bn = bxn * 128;
    const int tid = threadIdx.x;
    const int wid = tid >> 5, lane = tid & 31;
    const int wm = wid >> 2, wn = wid & 3;
    const int gid = lane >> 2, tig = lane & 3;

    float acc[2][4][4];
#pragma unroll
    for (int i = 0; i < 2; i++)
#pragma unroll
        for (int j = 0; j < 4; j++)
#pragma unroll
            for (int r = 0; r < 4; r++) acc[i][j][r] = 0.f;

    const int NT = K >> 6;
    uint4 av[4], wv[4];

    g_ldg(A, W, K, bm, bn, 0, tid, av, wv);
    g_sts(bufs[0], tid, av, wv);
    __syncthreads();
    g_ldg(A, W, K, bm, bn, 64, tid, av, wv);

    for (int kt = 0; kt < NT; kt++) {
        if (kt + 1 < NT) g_sts(bufs[(kt + 1) & 1], tid, av, wv);
        if (kt + 2 < NT) g_ldg(A, W, K, bm, bn, (kt + 2) * 64, tid, av, wv);
        g_compute(bufs[kt & 1], wm, wn, gid, tig, acc);
        __syncthreads();
    }

#pragma unroll
    for (int mt = 0; mt < 2; mt++)
#pragma unroll
        for (int nt = 0; nt < 4; nt++) {
            int row = bm + wm * 32 + mt * 16 + gid;
            int col = bn + wn * 32 + nt * 8 + tig * 2;
            float b0 = bias[col], b1 = bias[col + 1];
            float* c = acc[mt][nt];
            float v00 = c[0] + b0, v01 = c[1] + b1;
            float v10 = c[2] + b0, v11 = c[3] + b1;
            if (ES) {
                unsigned* C = (unsigned*)Cv;
                unsigned h, l;
                split_bf(v00, v01, h, l);
                *(uint2*)(C + (size_t)row * ldc + col) = make_uint2(h, l);
                split_bf(v10, v11, h, l);
                *(uint2*)(C + (size_t)(row + 8) * ldc + col) = make_uint2(h, l);
            } else {
                float* C = (float*)Cv;
                float* p0 = C + (size_t)row * ldc + col;
                float* p1 = C + (size_t)(row + 8) * ldc + col;
                p0[0] = v00; p0[1] = v01;
                p1[0] = v10; p1[1] = v11;
            }
        }
}

// ---------------------------------------------------------------------------
// Persistent LSTM (bf16x3), packed operands, k-step 64, group barriers.
// ---------------------------------------------------------------------------
struct PChain {
    const float*    xg0;  long dxg;
    unsigned*       ho0;  long dho;
    const unsigned* hp_init;
    const float*    cp_init;
    const unsigned* whh;
    float*          cbuf;
    int ldx, ldh, ldo, ldh_init;
};
struct PArgs { PChain c[2]; };

__device__ __forceinline__ float sigm(float x) { return 1.f / (1.f + expf(-x)); }

template<int BM>
__device__ __forceinline__ void l_ldg(const unsigned* hp, int ldh,
                                      const unsigned* whh,
                                      int H, int b0, int j0, int k0, int tid,
                                      uint4* av, uint4* wv) {
    {
        int r = tid >> 4, fc = tid & 15;
        av[0] = *(const uint4*)(hp + (size_t)(b0 + r) * ldh + k0 + fc * 4);
    }
#pragma unroll
    for (int i = 0; i < 8; i++) {
        int idx = tid + i * 512;
        int r = idx >> 4, fc = idx & 15;
        int g = r >> 6, jl = r & 63;
        wv[i] = *(const uint4*)(whh + (size_t)(g * H + j0 + jl) * H + k0 + fc * 4);
    }
}

template<int BM>
__device__ __forceinline__ void l_sts(unsigned* __restrict__ buf, int tid,
                                      const uint4* av, const uint4* wv) {
    unsigned* Ah = buf;
    unsigned* Al = buf + BM * 40;
    unsigned* Bh = buf + 2 * BM * 40;
    unsigned* Bl = buf + 2 * BM * 40 + 10240;
    {
        int r = tid >> 4, fc = tid & 15;
        int pa = r * 40 + permk2(fc * 2);
        int pb = r * 40 + permk2(fc * 2 + 1);
        Ah[pa] = av[0].x; Al[pa] = av[0].y; Ah[pb] = av[0].z; Al[pb] = av[0].w;
    }
#pragma unroll
    for (int i = 0; i < 8; i++) {
        int idx = tid + i * 512;
        int r = idx >> 4, fc = idx & 15;
        int pa = r * 40 + permk2(fc * 2);
        int pb = r * 40 + permk2(fc * 2 + 1);
        Bh[pa] = wv[i].x; Bl[pa] = wv[i].y; Bh[pb] = wv[i].z; Bl[pb] = wv[i].w;
    }
}

template<int BM>
__device__ __forceinline__ void l_compute(const unsigned* __restrict__ buf,
                                          int wn, int gid, int tig,
                                          float (&acc)[BM/16][2][4]) {
    constexpr int MT = BM / 16;
    const unsigned* Ah = buf;
    const unsigned* Al = buf + BM * 40;
    const unsigned* Bh = buf + 2 * BM * 40;
    const unsigned* Bl = buf + 2 * BM * 40 + 10240;
#pragma unroll
    for (int s = 0; s < 4; s++) {
        unsigned ah[MT][4], al[MT][4];
#pragma unroll
        for (int mt = 0; mt < MT; mt++) {
            int o = (mt * 16 + gid) * 40 + s * 8 + tig * 2;
            uint2 p = *(const uint2*)(Ah + o);
            uint2 q = *(const uint2*)(Ah + o + 320);
            ah[mt][0] = p.x; ah[mt][2] = p.y; ah[mt][1] = q.x; ah[mt][3] = q.y;
            uint2 r = *(const uint2*)(Al + o);
            uint2 t = *(const uint2*)(Al + o + 320);
            al[mt][0] = r.x; al[mt][2] = r.y; al[mt][1] = t.x; al[mt][3] = t.y;
        }
        unsigned bh[2][2], bl[2][2];
#pragma unroll
        for (int nj = 0; nj < 2; nj++) {
            int o = (wn * 16 + nj * 8 + gid) * 40 + s * 8 + tig * 2;
            uint2 p = *(const uint2*)(Bh + o);
            bh[nj][0] = p.x; bh[nj][1] = p.y;
            uint2 q = *(const uint2*)(Bl + o);
            bl[nj][0] = q.x; bl[nj][1] = q.y;
        }
#pragma unroll
        for (int mt = 0; mt < MT; mt++)
#pragma unroll
            for (int nj = 0; nj < 2; nj++) {
                float* c = acc[mt][nj];
                mma16bf(c, ah[mt], bh[nj]);
                mma16bf(c, ah[mt], bl[nj]);
                mma16bf(c, al[mt], bh[nj]);
            }
    }
}

template<int BM>
__device__ void lstm_body(const float* Xg, const unsigned* hp, const float* cp,
                          const unsigned* whh, unsigned* ho, float* co,
                          int ldx, int ldh, int ldo, int H,
                          unsigned* sb, int j0, int b0, int tid) {
    constexpr int MT = BM / 16;
    constexpr int BUFSZ = (2 * BM + 512) * 40;
    unsigned* bufs[2] = { sb, sb + BUFSZ };
    const int lane = tid & 31;
    const int wn = tid >> 5;
    const int gid = lane >> 2, tig = lane & 3;

    if (hp) {
        float acc[MT][2][4];
#pragma unroll
        for (int mt = 0; mt < MT; mt++)
#pragma unroll
            for (int nj = 0; nj < 2; nj++)
#pragma unroll
                for (int r = 0; r < 4; r++) acc[mt][nj][r] = 0.f;

        const int NKT = H >> 6;
        uint4 av[1], wv[8];

        l_ldg<BM>(hp, ldh, whh, H, b0, j0, 0, tid, av, wv);
        l_sts<BM>(bufs[0], tid, av, wv);
        __syncthreads();
        l_ldg<BM>(hp, ldh, whh, H, b0, j0, 64, tid, av, wv);

        for (int kt = 0; kt < NKT; kt++) {
            if (kt + 1 < NKT) l_sts<BM>(bufs[(kt + 1) & 1], tid, av, wv);
            if (kt + 2 < NKT) l_ldg<BM>(hp, ldh, whh, H, b0, j0, (kt + 2) * 64, tid, av, wv);
            l_compute<BM>(bufs[kt & 1], wn, gid, tig, acc);
            __syncthreads();
        }

        float* EB = (float*)sb;
#pragma unroll
        for (int mt = 0; mt < MT; mt++)
#pragma unroll
            for (int nj = 0; nj < 2; nj++) {
                int col = wn * 16 + nj * 8 + tig * 2;
                float* c = acc[mt][nj];
                EB[(mt * 16 + gid) * 260 + col]         = c[0];
                EB[(mt * 16 + gid) * 260 + col + 1]     = c[1];
                EB[(mt * 16 + gid + 8) * 260 + col]     = c[2];
                EB[(mt * 16 + gid + 8) * 260 + col + 1] = c[3];
            }
        __syncthreads();
    }

    const float* EB = (const float*)sb;
    const int jp = tid & 31;
    const int row0 = tid >> 5;
#pragma unroll
    for (int pass = 0; pass < BM / 16; pass++) {
        int bl_ = row0 + pass * 16;
        int b = b0 + bl_;
        const float* xr = Xg + (size_t)b * ldx;
        int j = j0 + 2 * jp;
        float2 a0 = {0.f, 0.f}, a1 = a0, a2 = a0, a3 = a0;
        if (hp) {
            const float* eb = EB + bl_ * 260 + 2 * jp;
            a0 = *(const float2*)(eb);
            a1 = *(const float2*)(eb + 64);
            a2 = *(const float2*)(eb + 128);
            a3 = *(const float2*)(eb + 192);
        }
        float2 xi = *(const float2*)(xr + j);
        float2 xf = *(const float2*)(xr + H + j);
        float2 xg = *(const float2*)(xr + 2 * H + j);
        float2 xo = *(const float2*)(xr + 3 * H + j);
        float2 cpv = {0.f, 0.f};
        if (cp) cpv = *(const float2*)(cp + (size_t)b * H + j);
        float cc0 = sigm(a1.x + xf.x) * cpv.x + sigm(a0.x + xi.x) * tanhf(a2.x + xg.x);
        float cc1 = sigm(a1.y + xf.y) * cpv.y + sigm(a0.y + xi.y) * tanhf(a2.y + xg.y);
        float h0f = sigm(a3.x + xo.x) * tanhf(cc0);
        float h1f = sigm(a3.y + xo.y) * tanhf(cc1);
        *(float2*)(co + (size_t)b * H + j) = make_float2(cc0, cc1);
        unsigned hh, hl;
        split_bf(h0f, h1f, hh, hl);
        *(uint2*)(ho + (size_t)b * ldo + j) = make_uint2(hh, hl);
    }
}

template<int BM>
__global__ __launch_bounds__(512) void lstm_persist(PArgs pa, int H, int nsteps) {
    extern __shared__ unsigned lsb[];
    const PChain ch = pa.c[blockIdx.z];
    const int j0 = blockIdx.x * 64;
    const int b0 = blockIdx.y * BM;
    const int tid = threadIdx.x;
    const size_t CB = 512 * (size_t)H;
    const int grp = blockIdx.z * gridDim.y + blockIdx.y;
    const unsigned nblk = gridDim.x;

    for (int t = 0; t < nsteps; t++) {
        const float* Xg = ch.xg0 + (long)t * ch.dxg;
        const unsigned* hp;
        const float* cp;
        int ldh;
        if (t == 0) { hp = ch.hp_init; cp = ch.cp_init; ldh = ch.ldh_init; }
        else {
            hp = ch.ho0 + (long)(t - 1) * ch.dho;
            cp = ch.cbuf + (size_t)(t & 1) * CB;
            ldh = ch.ldh;
        }
        unsigned* ho = ch.ho0 + (long)t * ch.dho;
        float* co = ch.cbuf + (size_t)((t + 1) & 1) * CB;

        lstm_body<BM>(Xg, hp, cp, ch.whh, ho, co,
                      ch.ldx, ldh, ch.ldo, H, lsb, j0, b0, tid);
        if (t + 1 < nsteps) group_barrier(grp, nblk);
    }
}

__global__ void build_h0c0(const unsigned* __restrict__ COw, const unsigned* __restrict__ TOw,
                           const float* __restrict__ ccf, const float* __restrict__ ctf,
                           unsigned* __restrict__ h0, float* __restrict__ c0) {
    int idx = blockIdx.x * blockDim.x + threadIdx.x;
    if (idx >= 512 * 512) return;
    int b = idx >> 9, w = idx & 511;
    unsigned hv;
    if (w < 256) hv = COw[((size_t)b * 48 + 47) * 512 + w];
    else         hv = TOw[((size_t)b * 16 + 15) * 512 + (w - 256)];
    h0[idx] = hv;
    float cv;
    if (w < 256) cv = ccf[b * 256 + w];
    else         cv = ctf[b * 256 + (w - 256)];
    c0[idx] = cv;
}

// ---------------------------------------------------------------------------
// Single-head attention with register micro-tiling; fp32 in, packed out.
// QK: thread tile 3q x KPT k.  AV: thread tile 3q x 4e with float4 V loads.
// ---------------------------------------------------------------------------
template<int KPT>
__global__ __launch_bounds__(256) void attn_kernel(
    const float* __restrict__ Q, const float* __restrict__ KV,
    unsigned* __restrict__ O)
{
    constexpr int Lk = KPT * 16;
    const int b = blockIdx.x;
    const int tid = threadIdx.x;
    __shared__ float Qs[48][68];
    __shared__ float Ks[48][68];
    __shared__ float s[48][49];

    const float* Qb = Q + (size_t)b * 48 * 512;
    const float* Kb = KV + (size_t)b * Lk * 1024;

    const int qg = tid >> 4;          // 0..15
    const int kg = tid & 15;          // 0..15
    const int q0 = qg * 3;

    float acc[3][KPT];
#pragma unroll
    for (int i = 0; i < 3; i++)
#pragma unroll
        for (int j = 0; j < KPT; j++) acc[i][j] = 0.f;

    for (int e0 = 0; e0 < 512; e0 += 64) {
        __syncthreads();
        for (int idx = tid; idx < 48 * 16; idx += 256) {
            int r = idx >> 4, cc = (idx & 15) << 2;
            *(float4*)&Qs[r][cc] = *(const float4*)(Qb + (size_t)r * 512 + e0 + cc);
        }
        for (int idx = tid; idx < Lk * 16; idx += 256) {
            int r = idx >> 4, cc = (idx & 15) << 2;
            *(float4*)&Ks[r][cc] = *(const float4*)(Kb + (size_t)r * 1024 + e0 + cc);
        }
        __syncthreads();
#pragma unroll 8
        for (int e = 0; e < 64; e++) {
            float a0 = Qs[q0][e], a1 = Qs[q0 + 1][e], a2 = Qs[q0 + 2][e];
#pragma unroll
            for (int j = 0; j < KPT; j++) {
                float bb = Ks[kg * KPT + j][e];
                acc[0][j] += a0 * bb;
                acc[1][j] += a1 * bb;
                acc[2][j] += a2 * bb;
            }
        }
    }
    __syncthreads();
    {
        const float scale = 0.04419417382415922f;   // 1/sqrt(512)
#pragma unroll
        for (int i = 0; i < 3; i++)
#pragma unroll
            for (int j = 0; j < KPT; j++)
                s[q0 + i][kg * KPT + j] = acc[i][j] * scale;
    }
    __syncthreads();
    if (tid < 48) {
        float m = -1e30f;
        for (int k = 0; k < Lk; k++) m = fmaxf(m, s[tid][k]);
        float sum = 0.f;
        for (int k = 0; k < Lk; k++) { float e = expf(s[tid][k] - m); s[tid][k] = e; sum += e; }
        float inv = 1.f / sum;
        for (int k = 0; k < Lk; k++) s[tid][k] *= inv;
    }
    __syncthreads();

    unsigned* Ob = O + (size_t)b * 48 * 512;
    const float* Vb = KV + (size_t)b * Lk * 1024 + 512;
    const int e0l = (tid & 15) * 4;   // e offset within chunk
    for (int e0 = 0; e0 < 512; e0 += 64) {
        for (int idx = tid; idx < Lk * 16; idx += 256) {
            int r = idx >> 4, cc = (idx & 15) << 2;
            *(float4*)&Ks[r][cc] = *(const float4*)(Vb + (size_t)r * 1024 + e0 + cc);
        }
        __syncthreads();
        float r0[4] = {0, 0, 0, 0}, r1[4] = {0, 0, 0, 0}, r2[4] = {0, 0, 0, 0};
        for (int k = 0; k < Lk; k++) {
            float4 v = *(const float4*)&Ks[k][e0l];
            float s0 = s[q0][k], s1 = s[q0 + 1][k], s2 = s[q0 + 2][k];
            r0[0] += s0 * v.x; r0[1] += s0 * v.y; r0[2] += s0 * v.z; r0[3] += s0 * v.w;
            r1[0] += s1 * v.x; r1[1] += s1 * v.y; r1[2] += s1 * v.z; r1[3] += s1 * v.w;
            r2[0] += s2 * v.x; r2[1] += s2 * v.y; r2[2] += s2 * v.z; r2[3] += s2 * v.w;
        }
        float* rows[3] = { r0, r1, r2 };
#pragma unroll
        for (int i = 0; i < 3; i++) {
            unsigned h0w, l0w, h1w, l1w;
            split_bf(rows[i][0], rows[i][1], h0w, l0w);
            split_bf(rows[i][2], rows[i][3], h1w, l1w);
            *(uint4*)(Ob + (size_t)(q0 + i) * 512 + e0 + e0l) =
                make_uint4(h0w, l0w, h1w, l1w);
        }
        __syncthreads();
    }
}

// ---------------------------------------------------------------------------
// Exact 1.5-entmax via warp bisection; one warp per row of 128.
// ---------------------------------------------------------------------------
__global__ __launch_bounds__(256) void entmax_kernel(
    const float* __restrict__ logits, float* __restrict__ out, int nrows)
{
    int row = blockIdx.x * 8 + (threadIdx.x >> 5);
    if (row >= nrows) return;
    int lane = threadIdx.x & 31;
    const float* x = logits + (size_t)row * 128;
    float z[4];
    float m = -1e30f;
#pragma unroll
    for (int i = 0; i < 4; i++) { z[i] = x[lane + 32 * i] * 0.5f; m = fmaxf(m, z[i]); }
#pragma unroll
    for (int o = 16; o; o >>= 1) m = fmaxf(m, __shfl_xor_sync(0xffffffffu, m, o));
#pragma unroll
    for (int i = 0; i < 4; i++) z[i] -= m;
    float lo = -1.f, hi = 0.f;
    for (int it = 0; it < 35; it++) {
        float tau = 0.5f * (lo + hi);
        float f = 0.f;
#pragma unroll
        for (int i = 0; i < 4; i++) { float d = fmaxf(z[i] - tau, 0.f); f += d * d; }
#pragma unroll
        for (int o = 16; o; o >>= 1) f += __shfl_xor_sync(0xffffffffu, f, o);
        if (f >= 1.f) lo = tau; else hi = tau;
    }
    float tau = 0.5f * (lo + hi);
    float* yo = out + (size_t)row * 128;
#pragma unroll
    for (int i = 0; i < 4; i++) { float d = fmaxf(z[i] - tau, 0.f); yo[lane + 32 * i] = d * d; }
}

// ---------------------------------------------------------------------------
extern "C" void kernel_launch(void* const* d_in, const int* in_sizes, int n_in,
                              void* d_out, int out_size) {
    const int*   li          = (const int*)  d_in[0];
    const float* char_seq    = (const float*)d_in[1];
    const float* tagset      = (const float*)d_in[2];
    const float* labels      = (const float*)d_in[3];
    const float* lang_embeds = (const float*)d_in[4];
    const float* c_w_ih_f    = (const float*)d_in[5];
    const float* c_w_hh_f    = (const float*)d_in[6];
    const float* c_b_f       = (const float*)d_in[7];
    const float* c_w_ih_b    = (const float*)d_in[8];
    const float* c_w_hh_b    = (const float*)d_in[9];
    const float* c_b_b       = (const float*)d_in[10];
    const float* t_w_ih_f    = (const float*)d_in[11];
    const float* t_w_hh_f    = (const float*)d_in[12];
    const float* t_b_f       = (const float*)d_in[13];
    const float* t_w_ih_b    = (const float*)d_in[14];
    const float* t_w_hh_b    = (const float*)d_in[15];
    const float* t_b_b       = (const float*)d_in[16];
    const float* cell_w_ih   = (const float*)d_in[17];
    const float* cell_w_hh   = (const float*)d_in[18];
    const float* cell_b      = (const float*)d_in[19];
    const float* ch_in_w     = (const float*)d_in[20];
    const float* ch_in_b     = (const float*)d_in[21];
    const float* ch_out_w    = (const float*)d_in[22];
    const float* ch_out_b    = (const float*)d_in[23];
    const float* tg_in_w     = (const float*)d_in[24];
    const float* tg_in_b     = (const float*)d_in[25];
    const float* tg_out_w    = (const float*)d_in[26];
    const float* tg_out_b    = (const float*)d_in[27];
    const float* fc_w        = (const float*)d_in[28];
    const float* fc_b        = (const float*)d_in[29];
    float* OUT = (float*)d_out;

    float* S = nullptr;
    cudaGetSymbolAddress((void**)&S, g_scratch);

    unsigned* CSw   = (unsigned*)(S + O_CS);
    unsigned* TSw   = (unsigned*)(S + O_TS);
    unsigned* DIw   = (unsigned*)(S + O_DECIN);
    unsigned* COw   = (unsigned*)(S + O_CO);
    unsigned* TOw   = (unsigned*)(S + O_TO);
    unsigned* HSw   = (unsigned*)(S + O_HS);
    unsigned* H0w   = (unsigned*)(S + O_H0);
    unsigned* OCw   = (unsigned*)(S + O_OC);
    unsigned* OTw   = (unsigned*)(S + O_OT);
    unsigned* CATw  = (unsigned*)(S + O_CAT);
    unsigned* PCIF  = (unsigned*)(S + O_PCIF);
    unsigned* PCIB  = (unsigned*)(S + O_PCIB);
    unsigned* PTIF  = (unsigned*)(S + O_PTIF);
    unsigned* PTIB  = (unsigned*)(S + O_PTIB);
    unsigned* PDI   = (unsigned*)(S + O_PDI);
    unsigned* PCHI  = (unsigned*)(S + O_PCHI);
    unsigned* PTGI  = (unsigned*)(S + O_PTGI);
    unsigned* PCHO  = (unsigned*)(S + O_PCHO);
    unsigned* PTGO  = (unsigned*)(S + O_PTGO);
    unsigned* PFC   = (unsigned*)(S + O_PFC);
    unsigned* PCHF  = (unsigned*)(S + O_PCHF);
    unsigned* PCHB  = (unsigned*)(S + O_PCHB);
    unsigned* PTHF  = (unsigned*)(S + O_PTHF);
    unsigned* PTHB  = (unsigned*)(S + O_PTHB);
    unsigned* PDHH  = (unsigned*)(S + O_PDHH);

    const int GSM = 163840;
    const int LSM = 184320;
    static bool attr_set = false;
    if (!attr_set) {
        cudaFuncSetAttribute(gemm_mma<false>, cudaFuncAttributeMaxDynamicSharedMemorySize, GSM);
        cudaFuncSetAttribute(gemm_mma<true>,  cudaFuncAttributeMaxDynamicSharedMemorySize, GSM);
        cudaFuncSetAttribute(lstm_persist<32>, cudaFuncAttributeMaxDynamicSharedMemorySize, LSM);
        attr_set = true;
    }

    // 1) input prep (packed) + one fused weight-packing launch
    prep_kernel<<<CDIV(2883584, 256), 256>>>(li, char_seq, tagset, lang_embeds, CSw, TSw);
    build_decin<<<CDIV(1572864, 256), 256>>>(labels, DIw);
    {
        WJobs J;
        const float* srcs[15] = { c_w_ih_f, c_w_ih_b, t_w_ih_f, t_w_ih_b, cell_w_ih,
                                  ch_in_w, tg_in_w, ch_out_w, tg_out_w, fc_w,
                                  c_w_hh_f, c_w_hh_b, t_w_hh_f, t_w_hh_b, cell_w_hh };
        unsigned* dsts[15]   = { PCIF, PCIB, PTIF, PTIB, PDI,
                                 PCHI, PTGI, PCHO, PTGO, PFC,
                                 PCHF, PCHB, PTHF, PTHB, PDHH };
        int sizes[15]        = { 98304, 98304, 65536, 65536, 131072,
                                 393216, 393216, 131072, 131072, 65536,
                                 131072, 131072, 131072, 131072, 524288 };
        int acc = 0;
        for (int i = 0; i < 15; i++) { J.src[i] = srcs[i]; J.dst[i] = dsts[i]; acc += sizes[i]; J.end[i] = acc; }
        wsplit_all<<<CDIV(acc, 256), 256>>>(J, acc);
    }

    // 2) input-projection GEMMs (fused same-shape pairs)
    {
        GemmDual P = { CSw, PCIF, c_b_f, S + O_XCF, CSw, PCIB, c_b_b, S + O_XCB, 8 };
        gemm_mma<false><<<dim3(16, 192), 512, GSM>>>(P, 24576, 1024, 192, 1024);
    }
    {
        GemmDual P = { TSw, PTIF, t_b_f, S + O_XTF, TSw, PTIB, t_b_b, S + O_XTB, 8 };
        gemm_mma<false><<<dim3(16, 64), 512, GSM>>>(P, 8192, 1024, 128, 1024);
    }
    {
        GemmDual P = { DIw, PDI, cell_b, S + O_XDEC, DIw, PDI, cell_b, S + O_XDEC, 1 << 30 };
        gemm_mma<false><<<dim3(16, 192), 512, GSM>>>(P, 24576, 2048, 128, 2048);
    }

    // 3) encoder recurrences
    {
        PArgs A;
        A.c[0] = { S + O_XCF, 1024, COw, 512,
                   nullptr, nullptr, PCHF, S + O_CCF,
                   48 * 1024, 48 * 512, 48 * 512, 0 };
        A.c[1] = { S + O_XCB + 47ll * 1024, -1024, COw + 47ll * 512 + 256, -512,
                   nullptr, nullptr, PCHB, S + O_CCB,
                   48 * 1024, 48 * 512, 48 * 512, 0 };
        lstm_persist<32><<<dim3(4, 16, 2), 512, LSM>>>(A, 256, 48);

        PArgs T;
        T.c[0] = { S + O_XTF, 1024, TOw, 512,
                   nullptr, nullptr, PTHF, S + O_CTF,
                   16 * 1024, 16 * 512, 16 * 512, 0 };
        T.c[1] = { S + O_XTB + 15ll * 1024, -1024, TOw + 15ll * 512 + 256, -512,
                   nullptr, nullptr, PTHB, S + O_CTB,
                   16 * 1024, 16 * 512, 16 * 512, 0 };
        lstm_persist<32><<<dim3(4, 16, 2), 512, LSM>>>(T, 256, 16);
    }

    // 4) initial decoder state
    build_h0c0<<<1024, 256>>>(COw, TOw, S + O_CCF, S + O_CTF, H0w, S + O_C0);

    // 5) decoder recurrence
    {
        PArgs D;
        D.c[0] = { S + O_XDEC, 2048, HSw, 512,
                   H0w, S + O_C0, PDHH, S + O_DC,
                   48 * 2048, 48 * 512, 48 * 512, 512 };
        D.c[1] = D.c[0];
        lstm_persist<32><<<dim3(8, 16, 1), 512, LSM>>>(D, 512, 48);
    }

    // 6) attention projections (Q pair fused; KV separate shapes)
    {
        GemmDual P = { HSw, PCHI, ch_in_b, S + O_QC, HSw, PTGI, tg_in_b, S + O_QT, 4 };
        gemm_mma<false><<<dim3(8, 192), 512, GSM>>>(P, 24576, 512, 512, 512);
    }
    {
        GemmDual P = { COw, PCHI + 512 * 512, ch_in_b + 512, S + O_KVC,
                       COw, PCHI + 512 * 512, ch_in_b + 512, S + O_KVC, 1 << 30 };
        gemm_mma<false><<<dim3(8, 192), 512, GSM>>>(P, 24576, 1024, 512, 1024);
    }
    {
        GemmDual P = { TOw, PTGI + 512 * 512, tg_in_b + 512, S + O_KVT,
                       TOw, PTGI + 512 * 512, tg_in_b + 512, S + O_KVT, 1 << 30 };
        gemm_mma<false><<<dim3(8, 64), 512, GSM>>>(P, 8192, 1024, 512, 1024);
    }

    // 7) attention cores (register-tiled, packed outputs)
    attn_kernel<3><<<512, 256>>>(S + O_QC, S + O_KVC, OCw);
    attn_kernel<1><<<512, 256>>>(S + O_QT, S + O_KVT, OTw);

    // 8) output projections into packed concat buffer (fused pair)
    {
        GemmDual P = { OCw, PCHO, ch_out_b, CATw, OTw, PTGO, tg_out_b, CATw + 512, 4 };
        gemm_mma<true><<<dim3(8, 192), 512, GSM>>>(P, 24576, 512, 512, 1024);
    }

    // 9) final FC + entmax15
    {
        GemmDual P = { CATw, PFC, fc_b, S + O_LOG, CATw, PFC, fc_b, S + O_LOG, 1 << 30 };
        gemm_mma<false><<<dim3(1, 192), 512, GSM>>>(P, 24576, 128, 1024, 128);
    }
    entmax_kernel<<<3072, 256>>>(S + O_LOG, OUT, 24576);
}